// round 1
// baseline (speedup 1.0000x reference)
#include <cuda_runtime.h>
#include <math.h>

// Problem constants (fixed by the dataset)
#define N_NODES 100000
#define N_EDGES 1600000
#define G_GRAPHS 64
#define HID 128
#define OUT_DIM 64

// ---------------------------------------------------------------------------
// Scratch (device globals; allocation-free per harness rules)
// ---------------------------------------------------------------------------
__device__ float g_bufA[N_NODES * HID];   // node features (layer output)
__device__ float g_bufB[N_NODES * HID];   // xw = x @ W
__device__ float g_deg[N_NODES];
__device__ float g_dinv[N_NODES];
__device__ float g_norm[N_EDGES];
__device__ float g_pooled[G_GRAPHS * HID];
__device__ float g_cnt[G_GRAPHS];
__device__ float g_h[2][G_GRAPHS * OUT_DIM];

// ---------------------------------------------------------------------------
// Degree / norm precompute (once per tower, reused over 6 layers)
// ---------------------------------------------------------------------------
__global__ void zero_deg_kernel() {
    int i = blockIdx.x * blockDim.x + threadIdx.x;
    if (i < N_NODES) g_deg[i] = 0.0f;
}

__global__ void deg_kernel(const int* __restrict__ ei, const float* __restrict__ ea) {
    int e = blockIdx.x * blockDim.x + threadIdx.x;
    if (e < N_EDGES) atomicAdd(&g_deg[ei[N_EDGES + e]], ea[e]);
}

__global__ void dinv_kernel() {
    int i = blockIdx.x * blockDim.x + threadIdx.x;
    // self loop adds weight 1 to every node's degree -> deg+1 > 0 always
    if (i < N_NODES) g_dinv[i] = rsqrtf(g_deg[i] + 1.0f);
}

__global__ void norm_kernel(const int* __restrict__ ei, const float* __restrict__ ea) {
    int e = blockIdx.x * blockDim.x + threadIdx.x;
    if (e < N_EDGES) {
        int si = ei[e];
        int di = ei[N_EDGES + e];
        g_norm[e] = g_dinv[si] * ea[e] * g_dinv[di];
    }
}

// ---------------------------------------------------------------------------
// GEMM: Y[n, c] = sum_k act(X[n, k]) * W[k, c]   (X: N x 128, W: 128 x 128)
// Block: 256 threads, tile = 64 rows x 128 cols, full K=128 pass.
// Dynamic smem: W (128x128) + X tile transposed (128 x 68 padded).
// ---------------------------------------------------------------------------
#define GEMM_SMEM_FLOATS (HID * HID + HID * 68)
#define GEMM_SMEM_BYTES  (GEMM_SMEM_FLOATS * 4)

__global__ void __launch_bounds__(256)
gemm_kernel(const float* __restrict__ Xext, int use_ext,
            const float* __restrict__ W, int tanh_in)
{
    extern __shared__ float smem[];
    float* sW = smem;              // [k*128 + c]
    float* sX = smem + HID * HID;  // [k*68 + r]  (transposed, padded)

    const float* X = use_ext ? Xext : g_bufA;
    const int tid  = threadIdx.x;
    const int row0 = blockIdx.x * 64;

    // Load W (16384 floats) as float4
    {
        const float4* W4 = (const float4*)W;
        float4* sW4 = (float4*)sW;
        #pragma unroll
        for (int i = 0; i < 16; ++i)
            sW4[tid + i * 256] = W4[tid + i * 256];
    }

    // Load X tile transposed: thread handles (r = idx&63, k4 = idx>>6)
    {
        const float4* X4 = (const float4*)X;
        #pragma unroll
        for (int j = 0; j < 8; ++j) {
            int idx = tid + j * 256;          // < 2048
            int r   = idx & 63;
            int k4  = idx >> 6;               // 0..31
            int grow = row0 + r;
            float4 v = make_float4(0.f, 0.f, 0.f, 0.f);
            if (grow < N_NODES) v = X4[grow * 32 + k4];
            if (tanh_in) {
                v.x = tanhf(v.x); v.y = tanhf(v.y);
                v.z = tanhf(v.z); v.w = tanhf(v.w);
            }
            int kb = k4 * 4;
            sX[(kb + 0) * 68 + r] = v.x;
            sX[(kb + 1) * 68 + r] = v.y;
            sX[(kb + 2) * 68 + r] = v.z;
            sX[(kb + 3) * 68 + r] = v.w;
        }
    }
    __syncthreads();

    const int tx = tid & 15;   // col group: cols tx*8 .. tx*8+7
    const int ty = tid >> 4;   // row group: rows ty*4 .. ty*4+3

    float acc[4][8];
    #pragma unroll
    for (int i = 0; i < 4; ++i)
        #pragma unroll
        for (int j = 0; j < 8; ++j) acc[i][j] = 0.0f;

    #pragma unroll 4
    for (int k = 0; k < HID; ++k) {
        float4 xv = *(const float4*)&sX[k * 68 + ty * 4];
        float4 wa = *(const float4*)&sW[k * HID + tx * 8];
        float4 wb = *(const float4*)&sW[k * HID + tx * 8 + 4];
        float xr[4] = { xv.x, xv.y, xv.z, xv.w };
        float wr[8] = { wa.x, wa.y, wa.z, wa.w, wb.x, wb.y, wb.z, wb.w };
        #pragma unroll
        for (int i = 0; i < 4; ++i)
            #pragma unroll
            for (int j = 0; j < 8; ++j)
                acc[i][j] += xr[i] * wr[j];
    }

    float4* Y4 = (float4*)g_bufB;
    #pragma unroll
    for (int i = 0; i < 4; ++i) {
        int grow = row0 + ty * 4 + i;
        if (grow < N_NODES) {
            float4 o0 = make_float4(acc[i][0], acc[i][1], acc[i][2], acc[i][3]);
            float4 o1 = make_float4(acc[i][4], acc[i][5], acc[i][6], acc[i][7]);
            Y4[grow * 32 + tx * 2 + 0] = o0;
            Y4[grow * 32 + tx * 2 + 1] = o1;
        }
    }
}

// ---------------------------------------------------------------------------
// Base: out[i] = bias + dinv[i]^2 * xw[i]   (self-loop term, non-atomic write)
// ---------------------------------------------------------------------------
__global__ void base_kernel(const float* __restrict__ bias) {
    int gt = blockIdx.x * blockDim.x + threadIdx.x;
    if (gt >= N_NODES * 32) return;
    int i = gt >> 5, q = gt & 31;
    float s = g_dinv[i];
    s = s * s;
    float4 b = ((const float4*)bias)[q];
    float4 v = ((const float4*)g_bufB)[i * 32 + q];
    float4 o = make_float4(b.x + s * v.x, b.y + s * v.y,
                           b.z + s * v.z, b.w + s * v.w);
    ((float4*)g_bufA)[i * 32 + q] = o;
}

// ---------------------------------------------------------------------------
// Edge aggregation: out[di] += norm[e] * xw[si]   (atomic)
// 32 threads per edge, one float4 slice each.
// ---------------------------------------------------------------------------
__global__ void edge_kernel(const int* __restrict__ ei) {
    int gt = blockIdx.x * blockDim.x + threadIdx.x;   // E*32 = 51.2M < 2^31
    if (gt >= N_EDGES * 32) return;
    int e = gt >> 5, q = gt & 31;
    int si = __ldg(&ei[e]);
    int di = __ldg(&ei[N_EDGES + e]);
    float nrm = g_norm[e];
    float4 v = ((const float4*)g_bufB)[si * 32 + q];
    float* dst = &g_bufA[di * HID + q * 4];
    atomicAdd(dst + 0, nrm * v.x);
    atomicAdd(dst + 1, nrm * v.y);
    atomicAdd(dst + 2, nrm * v.z);
    atomicAdd(dst + 3, nrm * v.w);
}

// ---------------------------------------------------------------------------
// Global mean pool (batch is sorted): register-accumulate, flush on change.
// Final layer activation (tanh) is fused here.
// ---------------------------------------------------------------------------
#define POOL_CHUNK 256

__global__ void pool_zero_kernel() {
    int i = blockIdx.x * blockDim.x + threadIdx.x;
    if (i < G_GRAPHS * HID) g_pooled[i] = 0.0f;
    if (i < G_GRAPHS) g_cnt[i] = 0.0f;
}

__global__ void pool_kernel(const int* __restrict__ batch) {
    int c  = threadIdx.x;                 // 128 channels
    int n0 = blockIdx.x * POOL_CHUNK;
    int n1 = n0 + POOL_CHUNK;
    if (n1 > N_NODES) n1 = N_NODES;
    if (n0 >= N_NODES) return;

    float acc = 0.0f;
    int cur = batch[n0];
    int run = 0;
    for (int n = n0; n < n1; ++n) {
        int g = batch[n];
        if (g != cur) {
            atomicAdd(&g_pooled[cur * HID + c], acc);
            if (c == 0) atomicAdd(&g_cnt[cur], (float)run);
            acc = 0.0f; run = 0; cur = g;
        }
        acc += tanhf(g_bufA[n * HID + c]);
        run++;
    }
    atomicAdd(&g_pooled[cur * HID + c], acc);
    if (c == 0) atomicAdd(&g_cnt[cur], (float)run);
}

// ---------------------------------------------------------------------------
// MLP head: fc1 (128->64, relu) + 5 x fc (64->64, relu). Single block.
// ---------------------------------------------------------------------------
__global__ void __launch_bounds__(512)
mlp_kernel(const float* __restrict__ fcW1, const float* __restrict__ fcb1,
           const float* __restrict__ fcW,  const float* __restrict__ fcb,
           int tower)
{
    __shared__ float ha[G_GRAPHS * OUT_DIM];
    __shared__ float hb[G_GRAPHS * OUT_DIM];
    int t = threadIdx.x;

    // fc1: h = relu(pooled/cnt @ fcW1 + fcb1)
    for (int idx = t; idx < G_GRAPHS * OUT_DIM; idx += 512) {
        int g = idx >> 6, o = idx & 63;
        float ic = g_cnt[g];
        ic = 1.0f / fmaxf(ic, 1.0f);
        float s = fcb1[o];
        #pragma unroll 4
        for (int k = 0; k < HID; ++k)
            s += g_pooled[g * HID + k] * ic * fcW1[k * OUT_DIM + o];
        ha[idx] = fmaxf(s, 0.0f);
    }
    __syncthreads();

    float* src = ha;
    float* dst = hb;
    for (int L = 0; L < 5; ++L) {
        const float* Wp = fcW + L * OUT_DIM * OUT_DIM;
        const float* bp = fcb + L * OUT_DIM;
        for (int idx = t; idx < G_GRAPHS * OUT_DIM; idx += 512) {
            int g = idx >> 6, o = idx & 63;
            float s = bp[o];
            #pragma unroll 8
            for (int k = 0; k < OUT_DIM; ++k)
                s += src[g * OUT_DIM + k] * Wp[k * OUT_DIM + o];
            dst[idx] = fmaxf(s, 0.0f);
        }
        __syncthreads();
        float* tmp = src; src = dst; dst = tmp;
    }

    for (int idx = t; idx < G_GRAPHS * OUT_DIM; idx += 512)
        g_h[tower][idx] = src[idx];
}

// ---------------------------------------------------------------------------
// Final: out[g] = || h1[g] - h2[g] ||_2
// ---------------------------------------------------------------------------
__global__ void final_kernel(float* __restrict__ out) {
    int g = threadIdx.x;
    if (g < G_GRAPHS) {
        float s = 0.0f;
        #pragma unroll 8
        for (int k = 0; k < OUT_DIM; ++k) {
            float d = g_h[0][g * OUT_DIM + k] - g_h[1][g * OUT_DIM + k];
            s += d * d;
        }
        out[g] = sqrtf(s);
    }
}

// ---------------------------------------------------------------------------
// Host launcher
// ---------------------------------------------------------------------------
extern "C" void kernel_launch(void* const* d_in, const int* in_sizes, int n_in,
                              void* d_out, int out_size)
{
    const float* x1  = (const float*)d_in[0];
    const int*   ei1 = (const int*)  d_in[1];
    const float* ea1 = (const float*)d_in[2];
    const int*   b1  = (const int*)  d_in[3];
    const float* x2  = (const float*)d_in[4];
    const int*   ei2 = (const int*)  d_in[5];
    const float* ea2 = (const float*)d_in[6];
    const int*   b2  = (const int*)  d_in[7];
    const float* convW = (const float*)d_in[8];
    const float* convB = (const float*)d_in[9];
    const float* fcW1  = (const float*)d_in[10];
    const float* fcb1  = (const float*)d_in[11];
    const float* fcW   = (const float*)d_in[12];
    const float* fcb   = (const float*)d_in[13];

    const bool ACTS[6] = { true, true, false, true, true, true };

    cudaFuncSetAttribute(gemm_kernel,
                         cudaFuncAttributeMaxDynamicSharedMemorySize,
                         GEMM_SMEM_BYTES);

    const int NB256_N = (N_NODES + 255) / 256;
    const int NB256_E = (N_EDGES + 255) / 256;
    const int GEMM_BLOCKS = (N_NODES + 63) / 64;
    const int BASE_BLOCKS = (N_NODES * 32 + 255) / 256;
    const int EDGE_BLOCKS = (N_EDGES * 32) / 256;   // divisible
    const int POOL_BLOCKS = (N_NODES + POOL_CHUNK - 1) / POOL_CHUNK;

    for (int tower = 0; tower < 2; ++tower) {
        const float* x  = tower ? x2  : x1;
        const int*   ei = tower ? ei2 : ei1;
        const float* ea = tower ? ea2 : ea1;
        const int*   bt = tower ? b2  : b1;

        zero_deg_kernel<<<NB256_N, 256>>>();
        deg_kernel<<<NB256_E, 256>>>(ei, ea);
        dinv_kernel<<<NB256_N, 256>>>();
        norm_kernel<<<NB256_E, 256>>>(ei, ea);

        for (int L = 0; L < 6; ++L) {
            int tanh_in = (L > 0) && ACTS[L - 1];
            gemm_kernel<<<GEMM_BLOCKS, 256, GEMM_SMEM_BYTES>>>(
                x, (L == 0) ? 1 : 0, convW + (size_t)L * HID * HID, tanh_in);
            base_kernel<<<BASE_BLOCKS, 256>>>(convB + L * HID);
            edge_kernel<<<EDGE_BLOCKS, 256>>>(ei);
        }

        pool_zero_kernel<<<(G_GRAPHS * HID + 255) / 256, 256>>>();
        pool_kernel<<<POOL_BLOCKS, 128>>>(bt);
        mlp_kernel<<<1, 512>>>(fcW1, fcb1, fcW, fcb, tower);
    }

    final_kernel<<<1, 64>>>((float*)d_out);
}

// round 2
// speedup vs baseline: 2.5426x; 2.5426x over previous
#include <cuda_runtime.h>
#include <math.h>

// Problem constants (fixed by the dataset)
#define N_NODES 100000
#define N_EDGES 1600000
#define G_GRAPHS 64
#define HID 128
#define OUT_DIM 64

#define SCAN_BLK 1024
#define N_SCAN_BLOCKS ((N_NODES + SCAN_BLK - 1) / SCAN_BLK)   // 98

// ---------------------------------------------------------------------------
// Scratch (device globals; allocation-free per harness rules)
// ---------------------------------------------------------------------------
__device__ float g_bufA[N_NODES * HID];   // node features (layer output)
__device__ float g_bufB[N_NODES * HID];   // xw = x @ W
__device__ float g_deg[N_NODES];
__device__ float g_dinv[N_NODES];
__device__ int   g_count[N_NODES];        // counts, then cursor
__device__ int   g_off[N_NODES + 1];      // CSR offsets (by dst)
__device__ int   g_blocksum[N_SCAN_BLOCKS];
__device__ int   g_srcs[N_EDGES];         // src node per sorted edge
__device__ float g_nrm[N_EDGES];          // norm per sorted edge
__device__ float g_pooled[G_GRAPHS * HID];
__device__ float g_cnt[G_GRAPHS];
__device__ float g_h[2][G_GRAPHS * OUT_DIM];

// ---------------------------------------------------------------------------
// Degree + counts (one pass over edges)
// ---------------------------------------------------------------------------
__global__ void zero_deg_kernel() {
    int i = blockIdx.x * blockDim.x + threadIdx.x;
    if (i < N_NODES) { g_deg[i] = 0.0f; g_count[i] = 0; }
}

__global__ void deg_count_kernel(const int* __restrict__ ei,
                                 const float* __restrict__ ea) {
    int e = blockIdx.x * blockDim.x + threadIdx.x;
    if (e < N_EDGES) {
        int di = ei[N_EDGES + e];
        atomicAdd(&g_deg[di], ea[e]);
        atomicAdd(&g_count[di], 1);
    }
}

__global__ void dinv_kernel() {
    int i = blockIdx.x * blockDim.x + threadIdx.x;
    // self loop adds weight 1 to every node's degree -> deg+1 > 0 always
    if (i < N_NODES) g_dinv[i] = rsqrtf(g_deg[i] + 1.0f);
}

// ---------------------------------------------------------------------------
// Exclusive scan of g_count -> g_off (3 kernels)
// ---------------------------------------------------------------------------
__global__ void __launch_bounds__(SCAN_BLK)
scan_block_kernel() {
    __shared__ int s[SCAN_BLK];
    int i = blockIdx.x * SCAN_BLK + threadIdx.x;
    int v = (i < N_NODES) ? g_count[i] : 0;
    s[threadIdx.x] = v;
    __syncthreads();
    // Hillis-Steele inclusive scan
    #pragma unroll
    for (int d = 1; d < SCAN_BLK; d <<= 1) {
        int t = (threadIdx.x >= d) ? s[threadIdx.x - d] : 0;
        __syncthreads();
        s[threadIdx.x] += t;
        __syncthreads();
    }
    if (i < N_NODES) g_off[i] = s[threadIdx.x] - v;   // exclusive
    if (threadIdx.x == SCAN_BLK - 1) g_blocksum[blockIdx.x] = s[threadIdx.x];
}

__global__ void scan_top_kernel() {
    if (threadIdx.x == 0) {
        int run = 0;
        for (int b = 0; b < N_SCAN_BLOCKS; ++b) {
            int t = g_blocksum[b];
            g_blocksum[b] = run;
            run += t;
        }
        g_off[N_NODES] = run;   // == N_EDGES
    }
}

__global__ void scan_add_kernel() {
    int i = blockIdx.x * blockDim.x + threadIdx.x;
    if (i < N_NODES) {
        int o = g_off[i] + g_blocksum[i >> 10];
        g_off[i] = o;
        g_count[i] = o;         // cursor for scatter
    }
}

// ---------------------------------------------------------------------------
// Scatter edges into dst-sorted order, norm fused
// ---------------------------------------------------------------------------
__global__ void scatter_kernel(const int* __restrict__ ei,
                               const float* __restrict__ ea) {
    int e = blockIdx.x * blockDim.x + threadIdx.x;
    if (e < N_EDGES) {
        int si = ei[e];
        int di = ei[N_EDGES + e];
        int pos = atomicAdd(&g_count[di], 1);
        g_srcs[pos] = si;
        g_nrm[pos]  = g_dinv[si] * ea[e] * g_dinv[di];
    }
}

// ---------------------------------------------------------------------------
// GEMM: Y[n, c] = sum_k act(X[n, k]) * W[k, c]   (X: N x 128, W: 128 x 128)
// ---------------------------------------------------------------------------
#define GEMM_SMEM_FLOATS (HID * HID + HID * 68)
#define GEMM_SMEM_BYTES  (GEMM_SMEM_FLOATS * 4)

__global__ void __launch_bounds__(256)
gemm_kernel(const float* __restrict__ Xext, int use_ext,
            const float* __restrict__ W, int tanh_in)
{
    extern __shared__ float smem[];
    float* sW = smem;              // [k*128 + c]
    float* sX = smem + HID * HID;  // [k*68 + r]  (transposed, padded)

    const float* X = use_ext ? Xext : g_bufA;
    const int tid  = threadIdx.x;
    const int row0 = blockIdx.x * 64;

    {
        const float4* W4 = (const float4*)W;
        float4* sW4 = (float4*)sW;
        #pragma unroll
        for (int i = 0; i < 16; ++i)
            sW4[tid + i * 256] = W4[tid + i * 256];
    }
    {
        const float4* X4 = (const float4*)X;
        #pragma unroll
        for (int j = 0; j < 8; ++j) {
            int idx = tid + j * 256;
            int r   = idx & 63;
            int k4  = idx >> 6;
            int grow = row0 + r;
            float4 v = make_float4(0.f, 0.f, 0.f, 0.f);
            if (grow < N_NODES) v = X4[grow * 32 + k4];
            if (tanh_in) {
                v.x = tanhf(v.x); v.y = tanhf(v.y);
                v.z = tanhf(v.z); v.w = tanhf(v.w);
            }
            int kb = k4 * 4;
            sX[(kb + 0) * 68 + r] = v.x;
            sX[(kb + 1) * 68 + r] = v.y;
            sX[(kb + 2) * 68 + r] = v.z;
            sX[(kb + 3) * 68 + r] = v.w;
        }
    }
    __syncthreads();

    const int tx = tid & 15;
    const int ty = tid >> 4;

    float acc[4][8];
    #pragma unroll
    for (int i = 0; i < 4; ++i)
        #pragma unroll
        for (int j = 0; j < 8; ++j) acc[i][j] = 0.0f;

    #pragma unroll 4
    for (int k = 0; k < HID; ++k) {
        float4 xv = *(const float4*)&sX[k * 68 + ty * 4];
        float4 wa = *(const float4*)&sW[k * HID + tx * 8];
        float4 wb = *(const float4*)&sW[k * HID + tx * 8 + 4];
        float xr[4] = { xv.x, xv.y, xv.z, xv.w };
        float wr[8] = { wa.x, wa.y, wa.z, wa.w, wb.x, wb.y, wb.z, wb.w };
        #pragma unroll
        for (int i = 0; i < 4; ++i)
            #pragma unroll
            for (int j = 0; j < 8; ++j)
                acc[i][j] += xr[i] * wr[j];
    }

    float4* Y4 = (float4*)g_bufB;
    #pragma unroll
    for (int i = 0; i < 4; ++i) {
        int grow = row0 + ty * 4 + i;
        if (grow < N_NODES) {
            float4 o0 = make_float4(acc[i][0], acc[i][1], acc[i][2], acc[i][3]);
            float4 o1 = make_float4(acc[i][4], acc[i][5], acc[i][6], acc[i][7]);
            Y4[grow * 32 + tx * 2 + 0] = o0;
            Y4[grow * 32 + tx * 2 + 1] = o1;
        }
    }
}

// ---------------------------------------------------------------------------
// Aggregation: warp per destination node, CSR gather, no atomics.
// out[i] = bias + dinv[i]^2 * xw[i] + sum_j nrm[j] * xw[src[j]]
// ---------------------------------------------------------------------------
__global__ void __launch_bounds__(256)
agg_kernel(const float* __restrict__ bias)
{
    int warp = (blockIdx.x * blockDim.x + threadIdx.x) >> 5;
    int lane = threadIdx.x & 31;
    if (warp >= N_NODES) return;

    const float4* xw4 = (const float4*)g_bufB;

    int beg = g_off[warp];
    int end = g_off[warp + 1];

    float s = g_dinv[warp];
    s = s * s;
    float4 b = ((const float4*)bias)[lane];
    float4 v = xw4[warp * 32 + lane];
    float4 acc = make_float4(b.x + s * v.x, b.y + s * v.y,
                             b.z + s * v.z, b.w + s * v.w);

    int j = beg;
    for (; j + 1 < end; j += 2) {
        int   s0 = g_srcs[j];
        int   s1 = g_srcs[j + 1];
        float n0 = g_nrm[j];
        float n1 = g_nrm[j + 1];
        float4 v0 = xw4[s0 * 32 + lane];
        float4 v1 = xw4[s1 * 32 + lane];
        acc.x += n0 * v0.x; acc.y += n0 * v0.y;
        acc.z += n0 * v0.z; acc.w += n0 * v0.w;
        acc.x += n1 * v1.x; acc.y += n1 * v1.y;
        acc.z += n1 * v1.z; acc.w += n1 * v1.w;
    }
    if (j < end) {
        int   s0 = g_srcs[j];
        float n0 = g_nrm[j];
        float4 v0 = xw4[s0 * 32 + lane];
        acc.x += n0 * v0.x; acc.y += n0 * v0.y;
        acc.z += n0 * v0.z; acc.w += n0 * v0.w;
    }

    ((float4*)g_bufA)[warp * 32 + lane] = acc;
}

// ---------------------------------------------------------------------------
// Global mean pool (batch is sorted): register-accumulate, flush on change.
// ---------------------------------------------------------------------------
#define POOL_CHUNK 256

__global__ void pool_zero_kernel() {
    int i = blockIdx.x * blockDim.x + threadIdx.x;
    if (i < G_GRAPHS * HID) g_pooled[i] = 0.0f;
    if (i < G_GRAPHS) g_cnt[i] = 0.0f;
}

__global__ void pool_kernel(const int* __restrict__ batch) {
    int c  = threadIdx.x;
    int n0 = blockIdx.x * POOL_CHUNK;
    int n1 = n0 + POOL_CHUNK;
    if (n1 > N_NODES) n1 = N_NODES;
    if (n0 >= N_NODES) return;

    float acc = 0.0f;
    int cur = batch[n0];
    int run = 0;
    for (int n = n0; n < n1; ++n) {
        int g = batch[n];
        if (g != cur) {
            atomicAdd(&g_pooled[cur * HID + c], acc);
            if (c == 0) atomicAdd(&g_cnt[cur], (float)run);
            acc = 0.0f; run = 0; cur = g;
        }
        acc += tanhf(g_bufA[n * HID + c]);
        run++;
    }
    atomicAdd(&g_pooled[cur * HID + c], acc);
    if (c == 0) atomicAdd(&g_cnt[cur], (float)run);
}

// ---------------------------------------------------------------------------
// MLP head: fc1 (128->64, relu) + 5 x fc (64->64, relu). Single block.
// ---------------------------------------------------------------------------
__global__ void __launch_bounds__(512)
mlp_kernel(const float* __restrict__ fcW1, const float* __restrict__ fcb1,
           const float* __restrict__ fcW,  const float* __restrict__ fcb,
           int tower)
{
    __shared__ float ha[G_GRAPHS * OUT_DIM];
    __shared__ float hb[G_GRAPHS * OUT_DIM];
    int t = threadIdx.x;

    for (int idx = t; idx < G_GRAPHS * OUT_DIM; idx += 512) {
        int g = idx >> 6, o = idx & 63;
        float ic = g_cnt[g];
        ic = 1.0f / fmaxf(ic, 1.0f);
        float s = fcb1[o];
        #pragma unroll 4
        for (int k = 0; k < HID; ++k)
            s += g_pooled[g * HID + k] * ic * fcW1[k * OUT_DIM + o];
        ha[idx] = fmaxf(s, 0.0f);
    }
    __syncthreads();

    float* src = ha;
    float* dst = hb;
    for (int L = 0; L < 5; ++L) {
        const float* Wp = fcW + L * OUT_DIM * OUT_DIM;
        const float* bp = fcb + L * OUT_DIM;
        for (int idx = t; idx < G_GRAPHS * OUT_DIM; idx += 512) {
            int g = idx >> 6, o = idx & 63;
            float s = bp[o];
            #pragma unroll 8
            for (int k = 0; k < OUT_DIM; ++k)
                s += src[g * OUT_DIM + k] * Wp[k * OUT_DIM + o];
            dst[idx] = fmaxf(s, 0.0f);
        }
        __syncthreads();
        float* tmp = src; src = dst; dst = tmp;
    }

    for (int idx = t; idx < G_GRAPHS * OUT_DIM; idx += 512)
        g_h[tower][idx] = src[idx];
}

__global__ void final_kernel(float* __restrict__ out) {
    int g = threadIdx.x;
    if (g < G_GRAPHS) {
        float s = 0.0f;
        #pragma unroll 8
        for (int k = 0; k < OUT_DIM; ++k) {
            float d = g_h[0][g * OUT_DIM + k] - g_h[1][g * OUT_DIM + k];
            s += d * d;
        }
        out[g] = sqrtf(s);
    }
}

// ---------------------------------------------------------------------------
// Host launcher
// ---------------------------------------------------------------------------
extern "C" void kernel_launch(void* const* d_in, const int* in_sizes, int n_in,
                              void* d_out, int out_size)
{
    const float* x1  = (const float*)d_in[0];
    const int*   ei1 = (const int*)  d_in[1];
    const float* ea1 = (const float*)d_in[2];
    const int*   b1  = (const int*)  d_in[3];
    const float* x2  = (const float*)d_in[4];
    const int*   ei2 = (const int*)  d_in[5];
    const float* ea2 = (const float*)d_in[6];
    const int*   b2  = (const int*)  d_in[7];
    const float* convW = (const float*)d_in[8];
    const float* convB = (const float*)d_in[9];
    const float* fcW1  = (const float*)d_in[10];
    const float* fcb1  = (const float*)d_in[11];
    const float* fcW   = (const float*)d_in[12];
    const float* fcb   = (const float*)d_in[13];

    const bool ACTS[6] = { true, true, false, true, true, true };

    cudaFuncSetAttribute(gemm_kernel,
                         cudaFuncAttributeMaxDynamicSharedMemorySize,
                         GEMM_SMEM_BYTES);

    const int NB256_N = (N_NODES + 255) / 256;
    const int NB256_E = (N_EDGES + 255) / 256;
    const int GEMM_BLOCKS = (N_NODES + 63) / 64;
    const int AGG_BLOCKS  = (N_NODES * 32 + 255) / 256;
    const int POOL_BLOCKS = (N_NODES + POOL_CHUNK - 1) / POOL_CHUNK;

    for (int tower = 0; tower < 2; ++tower) {
        const float* x  = tower ? x2  : x1;
        const int*   ei = tower ? ei2 : ei1;
        const float* ea = tower ? ea2 : ea1;
        const int*   bt = tower ? b2  : b1;

        // Build dst-sorted CSR + norms (once per tower, reused for 6 layers)
        zero_deg_kernel<<<NB256_N, 256>>>();
        deg_count_kernel<<<NB256_E, 256>>>(ei, ea);
        dinv_kernel<<<NB256_N, 256>>>();
        scan_block_kernel<<<N_SCAN_BLOCKS, SCAN_BLK>>>();
        scan_top_kernel<<<1, 32>>>();
        scan_add_kernel<<<NB256_N, 256>>>();
        scatter_kernel<<<NB256_E, 256>>>(ei, ea);

        for (int L = 0; L < 6; ++L) {
            int tanh_in = (L > 0) && ACTS[L - 1];
            gemm_kernel<<<GEMM_BLOCKS, 256, GEMM_SMEM_BYTES>>>(
                x, (L == 0) ? 1 : 0, convW + (size_t)L * HID * HID, tanh_in);
            agg_kernel<<<AGG_BLOCKS, 256>>>(convB + L * HID);
        }

        pool_zero_kernel<<<(G_GRAPHS * HID + 255) / 256, 256>>>();
        pool_kernel<<<POOL_BLOCKS, 128>>>(bt);
        mlp_kernel<<<1, 512>>>(fcW1, fcb1, fcW, fcb, tower);
    }

    final_kernel<<<1, 64>>>((float*)d_out);
}

// round 6
// speedup vs baseline: 2.8573x; 1.1238x over previous
#include <cuda_runtime.h>
#include <cuda_fp16.h>
#include <math.h>

// Problem constants (fixed by the dataset)
#define N_NODES 100000
#define N_EDGES 1600000
#define G_GRAPHS 64
#define HID 128
#define OUT_DIM 64

#define SCAN_BLK 1024
#define N_SCAN_BLOCKS ((N_NODES + SCAN_BLK - 1) / SCAN_BLK)

// ---------------------------------------------------------------------------
// Scratch (device globals; allocation-free per harness rules)
// ---------------------------------------------------------------------------
__device__ __half g_bufAh[N_NODES * HID];   // node features (fp16)
__device__ __half g_bufBh[N_NODES * HID];   // xw = x @ W (fp16)
__device__ float g_deg[N_NODES];
__device__ float g_dinv[N_NODES];
__device__ int   g_count[N_NODES];          // counts, then cursor
__device__ int   g_off[N_NODES + 1];        // CSR offsets (by dst)
__device__ int   g_blocksum[N_SCAN_BLOCKS];
__device__ int   g_srcs[N_EDGES];           // src node per sorted edge
__device__ float g_nrm[N_EDGES];            // norm per sorted edge
__device__ float g_pooled[G_GRAPHS * HID];
__device__ float g_cnt[G_GRAPHS];
__device__ float g_h[2][G_GRAPHS * OUT_DIM];

// ---------------------------------------------------------------------------
// fp32 -> fp16 conversion of input features
// ---------------------------------------------------------------------------
__global__ void conv_x_kernel(const float* __restrict__ x) {
    int i = blockIdx.x * blockDim.x + threadIdx.x;   // per 4 elements
    if (i < N_NODES * 32) {
        float4 v = ((const float4*)x)[i];
        uint2 o;
        *(__half2*)&o.x = __floats2half2_rn(v.x, v.y);
        *(__half2*)&o.y = __floats2half2_rn(v.z, v.w);
        ((uint2*)g_bufAh)[i] = o;
    }
}

// ---------------------------------------------------------------------------
// Degree + counts (one pass over edges)
// ---------------------------------------------------------------------------
__global__ void zero_deg_kernel() {
    int i = blockIdx.x * blockDim.x + threadIdx.x;
    if (i < N_NODES) { g_deg[i] = 0.0f; g_count[i] = 0; }
}

__global__ void deg_count_kernel(const int* __restrict__ ei,
                                 const float* __restrict__ ea) {
    int e = blockIdx.x * blockDim.x + threadIdx.x;
    if (e < N_EDGES) {
        int di = ei[N_EDGES + e];
        atomicAdd(&g_deg[di], ea[e]);
        atomicAdd(&g_count[di], 1);
    }
}

__global__ void dinv_kernel() {
    int i = blockIdx.x * blockDim.x + threadIdx.x;
    if (i < N_NODES) g_dinv[i] = rsqrtf(g_deg[i] + 1.0f);
}

// ---------------------------------------------------------------------------
// Exclusive scan of g_count -> g_off
// ---------------------------------------------------------------------------
__global__ void __launch_bounds__(SCAN_BLK)
scan_block_kernel() {
    __shared__ int s[SCAN_BLK];
    int i = blockIdx.x * SCAN_BLK + threadIdx.x;
    int v = (i < N_NODES) ? g_count[i] : 0;
    s[threadIdx.x] = v;
    __syncthreads();
    #pragma unroll
    for (int d = 1; d < SCAN_BLK; d <<= 1) {
        int t = (threadIdx.x >= d) ? s[threadIdx.x - d] : 0;
        __syncthreads();
        s[threadIdx.x] += t;
        __syncthreads();
    }
    if (i < N_NODES) g_off[i] = s[threadIdx.x] - v;
    if (threadIdx.x == SCAN_BLK - 1) g_blocksum[blockIdx.x] = s[threadIdx.x];
}

__global__ void scan_top_kernel() {
    if (threadIdx.x == 0) {
        int run = 0;
        for (int b = 0; b < N_SCAN_BLOCKS; ++b) {
            int t = g_blocksum[b];
            g_blocksum[b] = run;
            run += t;
        }
        g_off[N_NODES] = run;
    }
}

__global__ void scan_add_kernel() {
    int i = blockIdx.x * blockDim.x + threadIdx.x;
    if (i < N_NODES) {
        int o = g_off[i] + g_blocksum[i >> 10];
        g_off[i] = o;
        g_count[i] = o;
    }
}

__global__ void scatter_kernel(const int* __restrict__ ei,
                               const float* __restrict__ ea) {
    int e = blockIdx.x * blockDim.x + threadIdx.x;
    if (e < N_EDGES) {
        int si = ei[e];
        int di = ei[N_EDGES + e];
        int pos = atomicAdd(&g_count[di], 1);
        g_srcs[pos] = si;
        g_nrm[pos]  = g_dinv[si] * ea[e] * g_dinv[di];
    }
}

// ---------------------------------------------------------------------------
// GEMM (fp32 FFMA, proven in R2): bufB[n,c] = sum_k bufA[n,k] * W[k,c]
// Input/output buffers are fp16; W and compute are fp32.
// Block: 256 threads, tile = 64 rows x 128 cols, full K=128 pass.
// ---------------------------------------------------------------------------
#define GEMM_SMEM_FLOATS (HID * HID + HID * 68)
#define GEMM_SMEM_BYTES  (GEMM_SMEM_FLOATS * 4)

__global__ void __launch_bounds__(256)
gemm_kernel(const float* __restrict__ W)
{
    extern __shared__ float smem[];
    float* sW = smem;              // [k*128 + c]
    float* sX = smem + HID * HID;  // [k*68 + r]  (transposed, padded)

    const int tid  = threadIdx.x;
    const int row0 = blockIdx.x * 64;

    // Load W (16384 floats) as float4
    {
        const float4* W4 = (const float4*)W;
        float4* sW4 = (float4*)sW;
        #pragma unroll
        for (int i = 0; i < 16; ++i)
            sW4[tid + i * 256] = W4[tid + i * 256];
    }

    // Load X tile transposed (fp16 -> fp32): thread handles (r = idx&63, k4)
    {
        const uint2* X4 = (const uint2*)g_bufAh;   // 4 halfs per element
        #pragma unroll
        for (int j = 0; j < 8; ++j) {
            int idx = tid + j * 256;          // < 2048
            int r   = idx & 63;
            int k4  = idx >> 6;               // 0..31
            int grow = row0 + r;
            float2 va = make_float2(0.f, 0.f);
            float2 vb = make_float2(0.f, 0.f);
            if (grow < N_NODES) {
                uint2 h = X4[grow * 32 + k4];
                va = __half22float2(*(__half2*)&h.x);
                vb = __half22float2(*(__half2*)&h.y);
            }
            int kb = k4 * 4;
            sX[(kb + 0) * 68 + r] = va.x;
            sX[(kb + 1) * 68 + r] = va.y;
            sX[(kb + 2) * 68 + r] = vb.x;
            sX[(kb + 3) * 68 + r] = vb.y;
        }
    }
    __syncthreads();

    const int tx = tid & 15;   // col group: cols tx*8 .. tx*8+7
    const int ty = tid >> 4;   // row group: rows ty*4 .. ty*4+3

    float acc[4][8];
    #pragma unroll
    for (int i = 0; i < 4; ++i)
        #pragma unroll
        for (int j = 0; j < 8; ++j) acc[i][j] = 0.0f;

    #pragma unroll 4
    for (int k = 0; k < HID; ++k) {
        float4 xv = *(const float4*)&sX[k * 68 + ty * 4];
        float4 wa = *(const float4*)&sW[k * HID + tx * 8];
        float4 wb = *(const float4*)&sW[k * HID + tx * 8 + 4];
        float xr[4] = { xv.x, xv.y, xv.z, xv.w };
        float wr[8] = { wa.x, wa.y, wa.z, wa.w, wb.x, wb.y, wb.z, wb.w };
        #pragma unroll
        for (int i = 0; i < 4; ++i)
            #pragma unroll
            for (int j = 0; j < 8; ++j)
                acc[i][j] += xr[i] * wr[j];
    }

    // Store fp32 acc -> fp16 (8 halfs = one int4 per row per thread)
    #pragma unroll
    for (int i = 0; i < 4; ++i) {
        int grow = row0 + ty * 4 + i;
        if (grow < N_NODES) {
            int4 o;
            *(__half2*)&o.x = __floats2half2_rn(acc[i][0], acc[i][1]);
            *(__half2*)&o.y = __floats2half2_rn(acc[i][2], acc[i][3]);
            *(__half2*)&o.z = __floats2half2_rn(acc[i][4], acc[i][5]);
            *(__half2*)&o.w = __floats2half2_rn(acc[i][6], acc[i][7]);
            *(int4*)&g_bufBh[grow * HID + tx * 8] = o;
        }
    }
}

// ---------------------------------------------------------------------------
// Aggregation: warp per destination node, CSR gather, fp16 rows, fp32 acc.
// out = act( bias + dinv*dinv * xw[self] + sum_j nrm[j] * xw[src[j]] )
// ---------------------------------------------------------------------------
__global__ void __launch_bounds__(256)
agg_kernel(const float* __restrict__ bias, int act)
{
    int warp = (blockIdx.x * blockDim.x + threadIdx.x) >> 5;
    int lane = threadIdx.x & 31;
    if (warp >= N_NODES) return;

    const uint2* xw = (const uint2*)g_bufBh;   // 4 halfs per element

    int beg = g_off[warp];
    int end = g_off[warp + 1];

    float s = g_dinv[warp];
    s = s * s;
    float4 bb = ((const float4*)bias)[lane];
    uint2 self = xw[warp * 32 + lane];
    float2 f0 = __half22float2(*(__half2*)&self.x);
    float2 f1 = __half22float2(*(__half2*)&self.y);
    float ax = bb.x + s * f0.x;
    float ay = bb.y + s * f0.y;
    float az = bb.z + s * f1.x;
    float aw = bb.w + s * f1.y;

    int j = beg;
    for (; j + 1 < end; j += 2) {
        int   s0 = g_srcs[j];
        int   s1 = g_srcs[j + 1];
        float n0 = g_nrm[j];
        float n1 = g_nrm[j + 1];
        uint2 v0 = xw[s0 * 32 + lane];
        uint2 v1 = xw[s1 * 32 + lane];
        float2 g00 = __half22float2(*(__half2*)&v0.x);
        float2 g01 = __half22float2(*(__half2*)&v0.y);
        float2 g10 = __half22float2(*(__half2*)&v1.x);
        float2 g11 = __half22float2(*(__half2*)&v1.y);
        ax += n0 * g00.x; ay += n0 * g00.y; az += n0 * g01.x; aw += n0 * g01.y;
        ax += n1 * g10.x; ay += n1 * g10.y; az += n1 * g11.x; aw += n1 * g11.y;
    }
    if (j < end) {
        int   s0 = g_srcs[j];
        float n0 = g_nrm[j];
        uint2 v0 = xw[s0 * 32 + lane];
        float2 g00 = __half22float2(*(__half2*)&v0.x);
        float2 g01 = __half22float2(*(__half2*)&v0.y);
        ax += n0 * g00.x; ay += n0 * g00.y; az += n0 * g01.x; aw += n0 * g01.y;
    }

    if (act) {
        ax = tanhf(ax); ay = tanhf(ay); az = tanhf(az); aw = tanhf(aw);
    }
    uint2 o;
    *(__half2*)&o.x = __floats2half2_rn(ax, ay);
    *(__half2*)&o.y = __floats2half2_rn(az, aw);
    ((uint2*)g_bufAh)[warp * 32 + lane] = o;
}

// ---------------------------------------------------------------------------
// Global mean pool (batch is sorted): register-accumulate, flush on change.
// ---------------------------------------------------------------------------
#define POOL_CHUNK 256

__global__ void pool_zero_kernel() {
    int i = blockIdx.x * blockDim.x + threadIdx.x;
    if (i < G_GRAPHS * HID) g_pooled[i] = 0.0f;
    if (i < G_GRAPHS) g_cnt[i] = 0.0f;
}

__global__ void pool_kernel(const int* __restrict__ batch) {
    int c  = threadIdx.x;
    int n0 = blockIdx.x * POOL_CHUNK;
    int n1 = n0 + POOL_CHUNK;
    if (n1 > N_NODES) n1 = N_NODES;
    if (n0 >= N_NODES) return;

    float acc = 0.0f;
    int cur = batch[n0];
    int run = 0;
    for (int n = n0; n < n1; ++n) {
        int g = batch[n];
        if (g != cur) {
            atomicAdd(&g_pooled[cur * HID + c], acc);
            if (c == 0) atomicAdd(&g_cnt[cur], (float)run);
            acc = 0.0f; run = 0; cur = g;
        }
        acc += __half2float(g_bufAh[n * HID + c]);
        run++;
    }
    atomicAdd(&g_pooled[cur * HID + c], acc);
    if (c == 0) atomicAdd(&g_cnt[cur], (float)run);
}

// ---------------------------------------------------------------------------
// MLP head: fc1 (128->64, relu) + 5 x fc (64->64, relu). Single block.
// ---------------------------------------------------------------------------
__global__ void __launch_bounds__(512)
mlp_kernel(const float* __restrict__ fcW1, const float* __restrict__ fcb1,
           const float* __restrict__ fcW,  const float* __restrict__ fcb,
           int tower)
{
    __shared__ float ha[G_GRAPHS * OUT_DIM];
    __shared__ float hb[G_GRAPHS * OUT_DIM];
    int t = threadIdx.x;

    for (int idx = t; idx < G_GRAPHS * OUT_DIM; idx += 512) {
        int g = idx >> 6, o = idx & 63;
        float ic = g_cnt[g];
        ic = 1.0f / fmaxf(ic, 1.0f);
        float s = fcb1[o];
        #pragma unroll 4
        for (int k = 0; k < HID; ++k)
            s += g_pooled[g * HID + k] * ic * fcW1[k * OUT_DIM + o];
        ha[idx] = fmaxf(s, 0.0f);
    }
    __syncthreads();

    float* srcb = ha;
    float* dstb = hb;
    for (int L = 0; L < 5; ++L) {
        const float* Wp = fcW + L * OUT_DIM * OUT_DIM;
        const float* bp = fcb + L * OUT_DIM;
        for (int idx = t; idx < G_GRAPHS * OUT_DIM; idx += 512) {
            int g = idx >> 6, o = idx & 63;
            float s = bp[o];
            #pragma unroll 8
            for (int k = 0; k < OUT_DIM; ++k)
                s += srcb[g * OUT_DIM + k] * Wp[k * OUT_DIM + o];
            dstb[idx] = fmaxf(s, 0.0f);
        }
        __syncthreads();
        float* tmp = srcb; srcb = dstb; dstb = tmp;
    }

    for (int idx = t; idx < G_GRAPHS * OUT_DIM; idx += 512)
        g_h[tower][idx] = srcb[idx];
}

__global__ void final_kernel(float* __restrict__ out) {
    int g = threadIdx.x;
    if (g < G_GRAPHS) {
        float s = 0.0f;
        #pragma unroll 8
        for (int k = 0; k < OUT_DIM; ++k) {
            float d = g_h[0][g * OUT_DIM + k] - g_h[1][g * OUT_DIM + k];
            s += d * d;
        }
        out[g] = sqrtf(s);
    }
}

// ---------------------------------------------------------------------------
// Host launcher
// ---------------------------------------------------------------------------
extern "C" void kernel_launch(void* const* d_in, const int* in_sizes, int n_in,
                              void* d_out, int out_size)
{
    const float* x1  = (const float*)d_in[0];
    const int*   ei1 = (const int*)  d_in[1];
    const float* ea1 = (const float*)d_in[2];
    const int*   bt1 = (const int*)  d_in[3];
    const float* x2  = (const float*)d_in[4];
    const int*   ei2 = (const int*)  d_in[5];
    const float* ea2 = (const float*)d_in[6];
    const int*   bt2 = (const int*)  d_in[7];
    const float* convW = (const float*)d_in[8];
    const float* convB = (const float*)d_in[9];
    const float* fcW1  = (const float*)d_in[10];
    const float* fcb1  = (const float*)d_in[11];
    const float* fcW   = (const float*)d_in[12];
    const float* fcb   = (const float*)d_in[13];

    const bool ACTS[6] = { true, true, false, true, true, true };

    cudaFuncSetAttribute(gemm_kernel,
                         cudaFuncAttributeMaxDynamicSharedMemorySize,
                         GEMM_SMEM_BYTES);

    const int NB256_N = (N_NODES + 255) / 256;
    const int NB256_E = (N_EDGES + 255) / 256;
    const int GEMM_BLOCKS = (N_NODES + 63) / 64;
    const int AGG_BLOCKS  = (N_NODES * 32 + 255) / 256;
    const int POOL_BLOCKS = (N_NODES + POOL_CHUNK - 1) / POOL_CHUNK;

    for (int tower = 0; tower < 2; ++tower) {
        const float* x  = tower ? x2  : x1;
        const int*   ei = tower ? ei2 : ei1;
        const float* ea = tower ? ea2 : ea1;
        const int*   bt = tower ? bt2 : bt1;

        // Build dst-sorted CSR + norms (once per tower)
        zero_deg_kernel<<<NB256_N, 256>>>();
        deg_count_kernel<<<NB256_E, 256>>>(ei, ea);
        dinv_kernel<<<NB256_N, 256>>>();
        scan_block_kernel<<<N_SCAN_BLOCKS, SCAN_BLK>>>();
        scan_top_kernel<<<1, 32>>>();
        scan_add_kernel<<<NB256_N, 256>>>();
        scatter_kernel<<<NB256_E, 256>>>(ei, ea);

        // x -> fp16
        conv_x_kernel<<<(N_NODES * 32 + 255) / 256, 256>>>(x);

        for (int L = 0; L < 6; ++L) {
            gemm_kernel<<<GEMM_BLOCKS, 256, GEMM_SMEM_BYTES>>>(
                convW + (size_t)L * HID * HID);
            agg_kernel<<<AGG_BLOCKS, 256>>>(convB + L * HID, ACTS[L] ? 1 : 0);
        }

        pool_zero_kernel<<<(G_GRAPHS * HID + 255) / 256, 256>>>();
        pool_kernel<<<POOL_BLOCKS, 128>>>(bt);
        mlp_kernel<<<1, 512>>>(fcW1, fcb1, fcW, fcb, tower);
    }

    final_kernel<<<1, 64>>>((float*)d_out);
}

// round 7
// speedup vs baseline: 3.6308x; 1.2707x over previous
#include <cuda_runtime.h>
#include <cuda_fp16.h>
#include <math.h>

// Problem constants (fixed by the dataset)
#define N_NODES 100000
#define N_EDGES 1600000
#define G_GRAPHS 64
#define HID 128
#define OUT_DIM 64

#define SCAN_BLK 1024
#define N_SCAN_BLOCKS ((N_NODES + SCAN_BLK - 1) / SCAN_BLK)

// ---------------------------------------------------------------------------
// Scratch (device globals; allocation-free per harness rules)
// ---------------------------------------------------------------------------
__device__ __half g_bufAh[N_NODES * HID];   // node features (fp16)
__device__ __half g_bufBh[N_NODES * HID];   // xw = x @ W (fp16)
__device__ float g_deg[N_NODES];
__device__ float g_dinv[N_NODES];
__device__ int   g_count[N_NODES];          // counts, then cursor
__device__ int   g_off[N_NODES + 1];        // CSR offsets (by dst)
__device__ int   g_blocksum[N_SCAN_BLOCKS];
__device__ int   g_srcs[N_EDGES];           // src node per sorted edge
__device__ float g_nrm[N_EDGES];            // norm per sorted edge
__device__ float g_pooled[G_GRAPHS * HID];
__device__ float g_cnt[G_GRAPHS];
__device__ float g_h[2][G_GRAPHS * OUT_DIM];

// ---------------------------------------------------------------------------
// fp32 -> fp16 conversion of input features
// ---------------------------------------------------------------------------
__global__ void conv_x_kernel(const float* __restrict__ x) {
    int i = blockIdx.x * blockDim.x + threadIdx.x;   // per 4 elements
    if (i < N_NODES * 32) {
        float4 v = ((const float4*)x)[i];
        uint2 o;
        *(__half2*)&o.x = __floats2half2_rn(v.x, v.y);
        *(__half2*)&o.y = __floats2half2_rn(v.z, v.w);
        ((uint2*)g_bufAh)[i] = o;
    }
}

// ---------------------------------------------------------------------------
// Degree + counts (one pass over edges)
// ---------------------------------------------------------------------------
__global__ void zero_deg_kernel() {
    int i = blockIdx.x * blockDim.x + threadIdx.x;
    if (i < N_NODES) { g_deg[i] = 0.0f; g_count[i] = 0; }
}

__global__ void deg_count_kernel(const int* __restrict__ ei,
                                 const float* __restrict__ ea) {
    int e = blockIdx.x * blockDim.x + threadIdx.x;
    if (e < N_EDGES) {
        int di = ei[N_EDGES + e];
        atomicAdd(&g_deg[di], ea[e]);
        atomicAdd(&g_count[di], 1);
    }
}

__global__ void dinv_kernel() {
    int i = blockIdx.x * blockDim.x + threadIdx.x;
    if (i < N_NODES) g_dinv[i] = rsqrtf(g_deg[i] + 1.0f);
}

// ---------------------------------------------------------------------------
// Exclusive scan of g_count -> g_off
// ---------------------------------------------------------------------------
__global__ void __launch_bounds__(SCAN_BLK)
scan_block_kernel() {
    __shared__ int s[SCAN_BLK];
    int i = blockIdx.x * SCAN_BLK + threadIdx.x;
    int v = (i < N_NODES) ? g_count[i] : 0;
    s[threadIdx.x] = v;
    __syncthreads();
    #pragma unroll
    for (int d = 1; d < SCAN_BLK; d <<= 1) {
        int t = (threadIdx.x >= d) ? s[threadIdx.x - d] : 0;
        __syncthreads();
        s[threadIdx.x] += t;
        __syncthreads();
    }
    if (i < N_NODES) g_off[i] = s[threadIdx.x] - v;
    if (threadIdx.x == SCAN_BLK - 1) g_blocksum[blockIdx.x] = s[threadIdx.x];
}

__global__ void scan_top_kernel() {
    if (threadIdx.x == 0) {
        int run = 0;
        for (int b = 0; b < N_SCAN_BLOCKS; ++b) {
            int t = g_blocksum[b];
            g_blocksum[b] = run;
            run += t;
        }
        g_off[N_NODES] = run;
    }
}

__global__ void scan_add_kernel() {
    int i = blockIdx.x * blockDim.x + threadIdx.x;
    if (i < N_NODES) {
        int o = g_off[i] + g_blocksum[i >> 10];
        g_off[i] = o;
        g_count[i] = o;
    }
}

__global__ void scatter_kernel(const int* __restrict__ ei,
                               const float* __restrict__ ea) {
    int e = blockIdx.x * blockDim.x + threadIdx.x;
    if (e < N_EDGES) {
        int si = ei[e];
        int di = ei[N_EDGES + e];
        int pos = atomicAdd(&g_count[di], 1);
        g_srcs[pos] = si;
        g_nrm[pos]  = g_dinv[si] * ea[e] * g_dinv[di];
    }
}

// ---------------------------------------------------------------------------
// GEMM v2 (fp32 FFMA): bufB[n,c] = sum_k bufA[n,k] * W[k,c]
// Block tile 128(M) x 128(N), 256 threads, 8x8 per thread (4+4 split).
// X tile in smem as half2 row-pairs [k][rowpair]; W in smem fp32 [k][c].
// ---------------------------------------------------------------------------
#define XSTR2 64   // half2 entries per k-row (64 row-pairs)
#define GEMM_SMEM_BYTES (HID * HID * 4 + HID * XSTR2 * 4)   // 64KB + 32KB

__global__ void __launch_bounds__(256)
gemm_kernel(const float* __restrict__ W)
{
    extern __shared__ float smem[];
    float*   sW  = smem;                       // [k*128 + c], 64KB
    __half2* sX2 = (__half2*)(smem + HID * HID); // [k*XSTR2 + rp], 32KB

    const int tid  = threadIdx.x;
    const int row0 = blockIdx.x * 128;

    // Load W (16384 floats) as float4
    {
        const float4* W4 = (const float4*)W;
        float4* sW4 = (float4*)sW;
        #pragma unroll
        for (int i = 0; i < 16; ++i)
            sW4[tid + i * 256] = W4[tid + i * 256];
    }

    // Load X tile: 128 rows x 128 k (fp16), pack into [k][rowpair] half2.
    {
        const uint4* Xg = (const uint4*)g_bufAh;   // 8 halfs per uint4
        #pragma unroll
        for (int i = 0; i < 4; ++i) {
            int idx = tid + i * 256;      // 0..1023
            int rp  = idx & 63;           // row pair 0..63
            int k8  = idx >> 6;           // 0..15 (chunk of 8 k)
            int r0  = row0 + rp * 2;
            uint4 ua = make_uint4(0u, 0u, 0u, 0u);
            uint4 ub = make_uint4(0u, 0u, 0u, 0u);
            if (r0 < N_NODES)     ua = Xg[(size_t)r0 * 16 + k8];
            if (r0 + 1 < N_NODES) ub = Xg[(size_t)(r0 + 1) * 16 + k8];
            const __half2* pa = (const __half2*)&ua;
            const __half2* pb = (const __half2*)&ub;
            #pragma unroll
            for (int t2 = 0; t2 < 4; ++t2) {
                __half2 lo = __lows2half2(pa[t2], pb[t2]);
                __half2 hi = __highs2half2(pa[t2], pb[t2]);
                sX2[(k8 * 8 + t2 * 2 + 0) * XSTR2 + rp] = lo;
                sX2[(k8 * 8 + t2 * 2 + 1) * XSTR2 + rp] = hi;
            }
        }
    }
    __syncthreads();

    const int tx = tid & 15;   // col groups: tx*4 and 64+tx*4
    const int ty = tid >> 4;   // row groups: ty*4 and 64+ty*4

    float acc[8][8];
    #pragma unroll
    for (int i = 0; i < 8; ++i)
        #pragma unroll
        for (int j = 0; j < 8; ++j) acc[i][j] = 0.0f;

    #pragma unroll 4
    for (int k = 0; k < HID; ++k) {
        __half2 h0 = sX2[k * XSTR2 + ty * 2];
        __half2 h1 = sX2[k * XSTR2 + ty * 2 + 1];
        __half2 h2 = sX2[k * XSTR2 + 32 + ty * 2];
        __half2 h3 = sX2[k * XSTR2 + 32 + ty * 2 + 1];
        float2 f0 = __half22float2(h0);
        float2 f1 = __half22float2(h1);
        float2 f2 = __half22float2(h2);
        float2 f3 = __half22float2(h3);
        float xr[8] = { f0.x, f0.y, f1.x, f1.y, f2.x, f2.y, f3.x, f3.y };

        float4 wa = *(const float4*)&sW[k * HID + tx * 4];
        float4 wb = *(const float4*)&sW[k * HID + 64 + tx * 4];
        float wr[8] = { wa.x, wa.y, wa.z, wa.w, wb.x, wb.y, wb.z, wb.w };

        #pragma unroll
        for (int i = 0; i < 8; ++i)
            #pragma unroll
            for (int j = 0; j < 8; ++j)
                acc[i][j] += xr[i] * wr[j];
    }

    // Epilogue: fp32 acc -> fp16 global
    #pragma unroll
    for (int i = 0; i < 8; ++i) {
        int r = (i < 4) ? (ty * 4 + i) : (64 + ty * 4 + i - 4);
        int grow = row0 + r;
        if (grow < N_NODES) {
            uint2 o0, o1;
            *(__half2*)&o0.x = __floats2half2_rn(acc[i][0], acc[i][1]);
            *(__half2*)&o0.y = __floats2half2_rn(acc[i][2], acc[i][3]);
            *(__half2*)&o1.x = __floats2half2_rn(acc[i][4], acc[i][5]);
            *(__half2*)&o1.y = __floats2half2_rn(acc[i][6], acc[i][7]);
            *(uint2*)&g_bufBh[(size_t)grow * HID + tx * 4]      = o0;
            *(uint2*)&g_bufBh[(size_t)grow * HID + 64 + tx * 4] = o1;
        }
    }
}

// ---------------------------------------------------------------------------
// Aggregation v2: HALF-WARP per destination node (16 lanes x 8 channels).
// out = act( bias + dinv*dinv * xw[self] + sum_j nrm[j] * xw[src[j]] )
// ---------------------------------------------------------------------------
__device__ __forceinline__ void fma8(float* a, const uint4& v, float n) {
    const __half2* p = (const __half2*)&v;
    float2 q0 = __half22float2(p[0]);
    float2 q1 = __half22float2(p[1]);
    float2 q2 = __half22float2(p[2]);
    float2 q3 = __half22float2(p[3]);
    a[0] += n * q0.x; a[1] += n * q0.y;
    a[2] += n * q1.x; a[3] += n * q1.y;
    a[4] += n * q2.x; a[5] += n * q2.y;
    a[6] += n * q3.x; a[7] += n * q3.y;
}

__global__ void __launch_bounds__(256)
agg_kernel(const float* __restrict__ bias, int act)
{
    int node = (blockIdx.x * blockDim.x + threadIdx.x) >> 4;  // half-warp id
    int ln   = threadIdx.x & 15;
    if (node >= N_NODES) return;

    const uint4* xw = (const uint4*)g_bufBh;   // 8 halfs per uint4, 16 per row

    int beg = g_off[node];
    int end = g_off[node + 1];

    float s = g_dinv[node];
    s = s * s;
    float4 b0 = ((const float4*)bias)[ln * 2];
    float4 b1 = ((const float4*)bias)[ln * 2 + 1];
    float a[8] = { b0.x, b0.y, b0.z, b0.w, b1.x, b1.y, b1.z, b1.w };

    uint4 self = xw[(size_t)node * 16 + ln];
    fma8(a, self, s);

    int j = beg;
    for (; j + 1 < end; j += 2) {
        int   s0 = g_srcs[j];
        int   s1 = g_srcs[j + 1];
        float n0 = g_nrm[j];
        float n1 = g_nrm[j + 1];
        uint4 v0 = xw[(size_t)s0 * 16 + ln];
        uint4 v1 = xw[(size_t)s1 * 16 + ln];
        fma8(a, v0, n0);
        fma8(a, v1, n1);
    }
    if (j < end) {
        int   s0 = g_srcs[j];
        float n0 = g_nrm[j];
        uint4 v0 = xw[(size_t)s0 * 16 + ln];
        fma8(a, v0, n0);
    }

    if (act) {
        #pragma unroll
        for (int i = 0; i < 8; ++i) a[i] = tanhf(a[i]);
    }
    uint4 o;
    *(__half2*)&o.x = __floats2half2_rn(a[0], a[1]);
    *(__half2*)&o.y = __floats2half2_rn(a[2], a[3]);
    *(__half2*)&o.z = __floats2half2_rn(a[4], a[5]);
    *(__half2*)&o.w = __floats2half2_rn(a[6], a[7]);
    ((uint4*)g_bufAh)[(size_t)node * 16 + ln] = o;
}

// ---------------------------------------------------------------------------
// Global mean pool (batch is sorted): register-accumulate, flush on change.
// ---------------------------------------------------------------------------
#define POOL_CHUNK 256

__global__ void pool_zero_kernel() {
    int i = blockIdx.x * blockDim.x + threadIdx.x;
    if (i < G_GRAPHS * HID) g_pooled[i] = 0.0f;
    if (i < G_GRAPHS) g_cnt[i] = 0.0f;
}

__global__ void pool_kernel(const int* __restrict__ batch) {
    int c  = threadIdx.x;
    int n0 = blockIdx.x * POOL_CHUNK;
    int n1 = n0 + POOL_CHUNK;
    if (n1 > N_NODES) n1 = N_NODES;
    if (n0 >= N_NODES) return;

    float acc = 0.0f;
    int cur = batch[n0];
    int run = 0;
    for (int n = n0; n < n1; ++n) {
        int g = batch[n];
        if (g != cur) {
            atomicAdd(&g_pooled[cur * HID + c], acc);
            if (c == 0) atomicAdd(&g_cnt[cur], (float)run);
            acc = 0.0f; run = 0; cur = g;
        }
        acc += __half2float(g_bufAh[(size_t)n * HID + c]);
        run++;
    }
    atomicAdd(&g_pooled[cur * HID + c], acc);
    if (c == 0) atomicAdd(&g_cnt[cur], (float)run);
}

// ---------------------------------------------------------------------------
// MLP head: fc1 (128->64, relu) + 5 x fc (64->64, relu). Single block.
// ---------------------------------------------------------------------------
__global__ void __launch_bounds__(512)
mlp_kernel(const float* __restrict__ fcW1, const float* __restrict__ fcb1,
           const float* __restrict__ fcW,  const float* __restrict__ fcb,
           int tower)
{
    __shared__ float ha[G_GRAPHS * OUT_DIM];
    __shared__ float hb[G_GRAPHS * OUT_DIM];
    int t = threadIdx.x;

    for (int idx = t; idx < G_GRAPHS * OUT_DIM; idx += 512) {
        int g = idx >> 6, o = idx & 63;
        float ic = g_cnt[g];
        ic = 1.0f / fmaxf(ic, 1.0f);
        float s = fcb1[o];
        #pragma unroll 4
        for (int k = 0; k < HID; ++k)
            s += g_pooled[g * HID + k] * ic * fcW1[k * OUT_DIM + o];
        ha[idx] = fmaxf(s, 0.0f);
    }
    __syncthreads();

    float* srcb = ha;
    float* dstb = hb;
    for (int L = 0; L < 5; ++L) {
        const float* Wp = fcW + L * OUT_DIM * OUT_DIM;
        const float* bp = fcb + L * OUT_DIM;
        for (int idx = t; idx < G_GRAPHS * OUT_DIM; idx += 512) {
            int g = idx >> 6, o = idx & 63;
            float s = bp[o];
            #pragma unroll 8
            for (int k = 0; k < OUT_DIM; ++k)
                s += srcb[g * OUT_DIM + k] * Wp[k * OUT_DIM + o];
            dstb[idx] = fmaxf(s, 0.0f);
        }
        __syncthreads();
        float* tmp = srcb; srcb = dstb; dstb = tmp;
    }

    for (int idx = t; idx < G_GRAPHS * OUT_DIM; idx += 512)
        g_h[tower][idx] = srcb[idx];
}

__global__ void final_kernel(float* __restrict__ out) {
    int g = threadIdx.x;
    if (g < G_GRAPHS) {
        float s = 0.0f;
        #pragma unroll 8
        for (int k = 0; k < OUT_DIM; ++k) {
            float d = g_h[0][g * OUT_DIM + k] - g_h[1][g * OUT_DIM + k];
            s += d * d;
        }
        out[g] = sqrtf(s);
    }
}

// ---------------------------------------------------------------------------
// Host launcher
// ---------------------------------------------------------------------------
extern "C" void kernel_launch(void* const* d_in, const int* in_sizes, int n_in,
                              void* d_out, int out_size)
{
    const float* x1  = (const float*)d_in[0];
    const int*   ei1 = (const int*)  d_in[1];
    const float* ea1 = (const float*)d_in[2];
    const int*   bt1 = (const int*)  d_in[3];
    const float* x2  = (const float*)d_in[4];
    const int*   ei2 = (const int*)  d_in[5];
    const float* ea2 = (const float*)d_in[6];
    const int*   bt2 = (const int*)  d_in[7];
    const float* convW = (const float*)d_in[8];
    const float* convB = (const float*)d_in[9];
    const float* fcW1  = (const float*)d_in[10];
    const float* fcb1  = (const float*)d_in[11];
    const float* fcW   = (const float*)d_in[12];
    const float* fcb   = (const float*)d_in[13];

    const bool ACTS[6] = { true, true, false, true, true, true };

    cudaFuncSetAttribute(gemm_kernel,
                         cudaFuncAttributeMaxDynamicSharedMemorySize,
                         GEMM_SMEM_BYTES);

    const int NB256_N = (N_NODES + 255) / 256;
    const int NB256_E = (N_EDGES + 255) / 256;
    const int GEMM_BLOCKS = (N_NODES + 127) / 128;
    const int AGG_BLOCKS  = (N_NODES * 16 + 255) / 256;
    const int POOL_BLOCKS = (N_NODES + POOL_CHUNK - 1) / POOL_CHUNK;

    for (int tower = 0; tower < 2; ++tower) {
        const float* x  = tower ? x2  : x1;
        const int*   ei = tower ? ei2 : ei1;
        const float* ea = tower ? ea2 : ea1;
        const int*   bt = tower ? bt2 : bt1;

        // Build dst-sorted CSR + norms (once per tower)
        zero_deg_kernel<<<NB256_N, 256>>>();
        deg_count_kernel<<<NB256_E, 256>>>(ei, ea);
        dinv_kernel<<<NB256_N, 256>>>();
        scan_block_kernel<<<N_SCAN_BLOCKS, SCAN_BLK>>>();
        scan_top_kernel<<<1, 32>>>();
        scan_add_kernel<<<NB256_N, 256>>>();
        scatter_kernel<<<NB256_E, 256>>>(ei, ea);

        // x -> fp16
        conv_x_kernel<<<(N_NODES * 32 + 255) / 256, 256>>>(x);

        for (int L = 0; L < 6; ++L) {
            gemm_kernel<<<GEMM_BLOCKS, 256, GEMM_SMEM_BYTES>>>(
                convW + (size_t)L * HID * HID);
            agg_kernel<<<AGG_BLOCKS, 256>>>(convB + L * HID, ACTS[L] ? 1 : 0);
        }

        pool_zero_kernel<<<(G_GRAPHS * HID + 255) / 256, 256>>>();
        pool_kernel<<<POOL_BLOCKS, 128>>>(bt);
        mlp_kernel<<<1, 512>>>(fcW1, fcb1, fcW, fcb, tower);
    }

    final_kernel<<<1, 64>>>((float*)d_out);
}

// round 8
// speedup vs baseline: 3.6515x; 1.0057x over previous
#include <cuda_runtime.h>
#include <cuda_fp16.h>
#include <math.h>

// Problem constants (fixed by the dataset)
#define N_NODES 100000
#define N_EDGES 1600000
#define G_GRAPHS 64
#define HID 128
#define OUT_DIM 64

#define SCAN_BLK 1024
#define N_SCAN_BLOCKS ((N_NODES + SCAN_BLK - 1) / SCAN_BLK)

// ---------------------------------------------------------------------------
// Scratch (device globals; allocation-free per harness rules)
// ---------------------------------------------------------------------------
__device__ __half g_bufAh[N_NODES * HID];   // node features (fp16)
__device__ __half g_bufBh[N_NODES * HID];   // xw = x @ W (fp16)
__device__ float g_deg[N_NODES];
__device__ float g_dinv[N_NODES];
__device__ int   g_count[N_NODES];          // counts, then cursor
__device__ int   g_off[N_NODES + 1];        // CSR offsets (by dst)
__device__ int   g_blocksum[N_SCAN_BLOCKS];
__device__ int   g_srcs[N_EDGES];           // src node per sorted edge
__device__ float g_nrm[N_EDGES];            // norm per sorted edge
__device__ float g_pooled[G_GRAPHS * HID];
__device__ float g_cnt[G_GRAPHS];
__device__ float g_h[2][G_GRAPHS * OUT_DIM];

// ---------------------------------------------------------------------------
// fp32 -> fp16 conversion of input features
// ---------------------------------------------------------------------------
__global__ void conv_x_kernel(const float* __restrict__ x) {
    int i = blockIdx.x * blockDim.x + threadIdx.x;   // per 4 elements
    if (i < N_NODES * 32) {
        float4 v = ((const float4*)x)[i];
        uint2 o;
        *(__half2*)&o.x = __floats2half2_rn(v.x, v.y);
        *(__half2*)&o.y = __floats2half2_rn(v.z, v.w);
        ((uint2*)g_bufAh)[i] = o;
    }
}

// ---------------------------------------------------------------------------
// Degree + counts (one pass over edges)
// ---------------------------------------------------------------------------
__global__ void zero_deg_kernel() {
    int i = blockIdx.x * blockDim.x + threadIdx.x;
    if (i < N_NODES) { g_deg[i] = 0.0f; g_count[i] = 0; }
}

__global__ void deg_count_kernel(const int* __restrict__ ei,
                                 const float* __restrict__ ea) {
    int e = blockIdx.x * blockDim.x + threadIdx.x;
    if (e < N_EDGES) {
        int di = ei[N_EDGES + e];
        atomicAdd(&g_deg[di], ea[e]);
        atomicAdd(&g_count[di], 1);
    }
}

__global__ void dinv_kernel() {
    int i = blockIdx.x * blockDim.x + threadIdx.x;
    if (i < N_NODES) g_dinv[i] = rsqrtf(g_deg[i] + 1.0f);
}

// ---------------------------------------------------------------------------
// Exclusive scan of g_count -> g_off
// ---------------------------------------------------------------------------
__global__ void __launch_bounds__(SCAN_BLK)
scan_block_kernel() {
    __shared__ int s[SCAN_BLK];
    int i = blockIdx.x * SCAN_BLK + threadIdx.x;
    int v = (i < N_NODES) ? g_count[i] : 0;
    s[threadIdx.x] = v;
    __syncthreads();
    #pragma unroll
    for (int d = 1; d < SCAN_BLK; d <<= 1) {
        int t = (threadIdx.x >= d) ? s[threadIdx.x - d] : 0;
        __syncthreads();
        s[threadIdx.x] += t;
        __syncthreads();
    }
    if (i < N_NODES) g_off[i] = s[threadIdx.x] - v;
    if (threadIdx.x == SCAN_BLK - 1) g_blocksum[blockIdx.x] = s[threadIdx.x];
}

__global__ void scan_top_kernel() {
    if (threadIdx.x == 0) {
        int run = 0;
        for (int b = 0; b < N_SCAN_BLOCKS; ++b) {
            int t = g_blocksum[b];
            g_blocksum[b] = run;
            run += t;
        }
        g_off[N_NODES] = run;
    }
}

__global__ void scan_add_kernel() {
    int i = blockIdx.x * blockDim.x + threadIdx.x;
    if (i < N_NODES) {
        int o = g_off[i] + g_blocksum[i >> 10];
        g_off[i] = o;
        g_count[i] = o;
    }
}

__global__ void scatter_kernel(const int* __restrict__ ei,
                               const float* __restrict__ ea) {
    int e = blockIdx.x * blockDim.x + threadIdx.x;
    if (e < N_EDGES) {
        int si = ei[e];
        int di = ei[N_EDGES + e];
        int pos = atomicAdd(&g_count[di], 1);
        g_srcs[pos] = si;
        g_nrm[pos]  = g_dinv[si] * ea[e] * g_dinv[di];
    }
}

// ---------------------------------------------------------------------------
// GEMM v3 (HFMA2): bufB[n,c] = sum_k bufA[n,k] * W[k,c]
// Block tile 128(M) x 128(N), 256 threads, 8x8 per thread (4+4 split).
// X in smem as half2 row-pairs [k][rowpair]; W in smem as half2 col-pairs.
// fp16 accumulate over chunks of 8 k-steps, promoted to fp32 accumulators.
// ---------------------------------------------------------------------------
#define XSTR2 64   // half2 entries per k-row
#define WSTR2 64
#define GEMM_SMEM_BYTES (HID * WSTR2 * 4 + HID * XSTR2 * 4)   // 32KB + 32KB

__global__ void __launch_bounds__(256, 2)
gemm_kernel(const float* __restrict__ W)
{
    extern __shared__ __half2 smem2[];
    __half2* sW2 = smem2;               // [k*WSTR2 + cp]
    __half2* sX2 = smem2 + HID * WSTR2; // [k*XSTR2 + rp]

    const int tid  = threadIdx.x;
    const int row0 = blockIdx.x * 128;

    // Load W (16384 floats), convert to half2 col-pairs
    {
        const float4* W4 = (const float4*)W;
        #pragma unroll
        for (int i = 0; i < 16; ++i) {
            int idx = tid + i * 256;     // float4 index: 0..4095
            int k  = idx >> 5;           // 32 float4 per k-row
            int c4 = idx & 31;           // which group of 4 cols
            float4 v = W4[idx];
            uint2 o;
            *(__half2*)&o.x = __floats2half2_rn(v.x, v.y);
            *(__half2*)&o.y = __floats2half2_rn(v.z, v.w);
            *(uint2*)&sW2[k * WSTR2 + c4 * 2] = o;
        }
    }

    // Load X tile: 128 rows x 128 k (fp16), pack into [k][rowpair] half2.
    {
        const uint4* Xg = (const uint4*)g_bufAh;   // 8 halfs per uint4
        #pragma unroll
        for (int i = 0; i < 4; ++i) {
            int idx = tid + i * 256;      // 0..1023
            int rp  = idx & 63;           // row pair 0..63
            int k8  = idx >> 6;           // 0..15 (chunk of 8 k)
            int r0  = row0 + rp * 2;
            uint4 ua = make_uint4(0u, 0u, 0u, 0u);
            uint4 ub = make_uint4(0u, 0u, 0u, 0u);
            if (r0 < N_NODES)     ua = Xg[(size_t)r0 * 16 + k8];
            if (r0 + 1 < N_NODES) ub = Xg[(size_t)(r0 + 1) * 16 + k8];
            const __half2* pa = (const __half2*)&ua;
            const __half2* pb = (const __half2*)&ub;
            #pragma unroll
            for (int t2 = 0; t2 < 4; ++t2) {
                __half2 lo = __lows2half2(pa[t2], pb[t2]);
                __half2 hi = __highs2half2(pa[t2], pb[t2]);
                sX2[(k8 * 8 + t2 * 2 + 0) * XSTR2 + rp] = lo;
                sX2[(k8 * 8 + t2 * 2 + 1) * XSTR2 + rp] = hi;
            }
        }
    }
    __syncthreads();

    const int tx = tid & 15;   // col groups: tx*4 and 64+tx*4
    const int ty = tid >> 4;   // row groups: ty*4 and 64+ty*4

    float accf[8][8];
    #pragma unroll
    for (int i = 0; i < 8; ++i)
        #pragma unroll
        for (int j = 0; j < 8; ++j) accf[i][j] = 0.0f;

    #pragma unroll
    for (int kc = 0; kc < 16; ++kc) {        // 16 chunks of 8 k
        __half2 acc2[8][4];
        #pragma unroll
        for (int i = 0; i < 8; ++i)
            #pragma unroll
            for (int j = 0; j < 4; ++j)
                acc2[i][j] = __floats2half2_rn(0.0f, 0.0f);

        #pragma unroll
        for (int kk = 0; kk < 8; ++kk) {
            int k = kc * 8 + kk;
            __half2 xa = sX2[k * XSTR2 + ty * 2];
            __half2 xb = sX2[k * XSTR2 + ty * 2 + 1];
            __half2 xc = sX2[k * XSTR2 + 32 + ty * 2];
            __half2 xd = sX2[k * XSTR2 + 32 + ty * 2 + 1];
            __half2 xr[8];
            xr[0] = __half2half2(__low2half(xa));
            xr[1] = __half2half2(__high2half(xa));
            xr[2] = __half2half2(__low2half(xb));
            xr[3] = __half2half2(__high2half(xb));
            xr[4] = __half2half2(__low2half(xc));
            xr[5] = __half2half2(__high2half(xc));
            xr[6] = __half2half2(__low2half(xd));
            xr[7] = __half2half2(__high2half(xd));

            __half2 wr[4];
            wr[0] = sW2[k * WSTR2 + tx * 2];
            wr[1] = sW2[k * WSTR2 + tx * 2 + 1];
            wr[2] = sW2[k * WSTR2 + 32 + tx * 2];
            wr[3] = sW2[k * WSTR2 + 32 + tx * 2 + 1];

            #pragma unroll
            for (int i = 0; i < 8; ++i)
                #pragma unroll
                for (int j = 0; j < 4; ++j)
                    acc2[i][j] = __hfma2(xr[i], wr[j], acc2[i][j]);
        }

        // Promote chunk to fp32
        #pragma unroll
        for (int i = 0; i < 8; ++i)
            #pragma unroll
            for (int j = 0; j < 4; ++j) {
                float2 f = __half22float2(acc2[i][j]);
                accf[i][j * 2]     += f.x;
                accf[i][j * 2 + 1] += f.y;
            }
    }

    // Epilogue: fp32 acc -> fp16 global
    #pragma unroll
    for (int i = 0; i < 8; ++i) {
        int r = (i < 4) ? (ty * 4 + i) : (64 + ty * 4 + i - 4);
        int grow = row0 + r;
        if (grow < N_NODES) {
            uint2 o0, o1;
            *(__half2*)&o0.x = __floats2half2_rn(accf[i][0], accf[i][1]);
            *(__half2*)&o0.y = __floats2half2_rn(accf[i][2], accf[i][3]);
            *(__half2*)&o1.x = __floats2half2_rn(accf[i][4], accf[i][5]);
            *(__half2*)&o1.y = __floats2half2_rn(accf[i][6], accf[i][7]);
            *(uint2*)&g_bufBh[(size_t)grow * HID + tx * 4]      = o0;
            *(uint2*)&g_bufBh[(size_t)grow * HID + 64 + tx * 4] = o1;
        }
    }
}

// ---------------------------------------------------------------------------
// Aggregation: HALF-WARP per destination node (16 lanes x 8 channels).
// out = act( bias + dinv*dinv * xw[self] + sum_j nrm[j] * xw[src[j]] )
// ---------------------------------------------------------------------------
__device__ __forceinline__ void fma8(float* a, const uint4& v, float n) {
    const __half2* p = (const __half2*)&v;
    float2 q0 = __half22float2(p[0]);
    float2 q1 = __half22float2(p[1]);
    float2 q2 = __half22float2(p[2]);
    float2 q3 = __half22float2(p[3]);
    a[0] += n * q0.x; a[1] += n * q0.y;
    a[2] += n * q1.x; a[3] += n * q1.y;
    a[4] += n * q2.x; a[5] += n * q2.y;
    a[6] += n * q3.x; a[7] += n * q3.y;
}

__global__ void __launch_bounds__(256)
agg_kernel(const float* __restrict__ bias, int act)
{
    int node = (blockIdx.x * blockDim.x + threadIdx.x) >> 4;  // half-warp id
    int ln   = threadIdx.x & 15;
    if (node >= N_NODES) return;

    const uint4* xw = (const uint4*)g_bufBh;   // 8 halfs per uint4, 16 per row

    int beg = g_off[node];
    int end = g_off[node + 1];

    float s = g_dinv[node];
    s = s * s;
    float4 b0 = ((const float4*)bias)[ln * 2];
    float4 b1 = ((const float4*)bias)[ln * 2 + 1];
    float a[8] = { b0.x, b0.y, b0.z, b0.w, b1.x, b1.y, b1.z, b1.w };

    uint4 self = xw[(size_t)node * 16 + ln];
    fma8(a, self, s);

    int j = beg;
    for (; j + 1 < end; j += 2) {
        int   s0 = g_srcs[j];
        int   s1 = g_srcs[j + 1];
        float n0 = g_nrm[j];
        float n1 = g_nrm[j + 1];
        uint4 v0 = xw[(size_t)s0 * 16 + ln];
        uint4 v1 = xw[(size_t)s1 * 16 + ln];
        fma8(a, v0, n0);
        fma8(a, v1, n1);
    }
    if (j < end) {
        int   s0 = g_srcs[j];
        float n0 = g_nrm[j];
        uint4 v0 = xw[(size_t)s0 * 16 + ln];
        fma8(a, v0, n0);
    }

    if (act) {
        #pragma unroll
        for (int i = 0; i < 8; ++i) a[i] = tanhf(a[i]);
    }
    uint4 o;
    *(__half2*)&o.x = __floats2half2_rn(a[0], a[1]);
    *(__half2*)&o.y = __floats2half2_rn(a[2], a[3]);
    *(__half2*)&o.z = __floats2half2_rn(a[4], a[5]);
    *(__half2*)&o.w = __floats2half2_rn(a[6], a[7]);
    ((uint4*)g_bufAh)[(size_t)node * 16 + ln] = o;
}

// ---------------------------------------------------------------------------
// Global mean pool (batch is sorted): register-accumulate, flush on change.
// ---------------------------------------------------------------------------
#define POOL_CHUNK 256

__global__ void pool_zero_kernel() {
    int i = blockIdx.x * blockDim.x + threadIdx.x;
    if (i < G_GRAPHS * HID) g_pooled[i] = 0.0f;
    if (i < G_GRAPHS) g_cnt[i] = 0.0f;
}

__global__ void pool_kernel(const int* __restrict__ batch) {
    int c  = threadIdx.x;
    int n0 = blockIdx.x * POOL_CHUNK;
    int n1 = n0 + POOL_CHUNK;
    if (n1 > N_NODES) n1 = N_NODES;
    if (n0 >= N_NODES) return;

    float acc = 0.0f;
    int cur = batch[n0];
    int run = 0;
    for (int n = n0; n < n1; ++n) {
        int g = batch[n];
        if (g != cur) {
            atomicAdd(&g_pooled[cur * HID + c], acc);
            if (c == 0) atomicAdd(&g_cnt[cur], (float)run);
            acc = 0.0f; run = 0; cur = g;
        }
        acc += __half2float(g_bufAh[(size_t)n * HID + c]);
        run++;
    }
    atomicAdd(&g_pooled[cur * HID + c], acc);
    if (c == 0) atomicAdd(&g_cnt[cur], (float)run);
}

// ---------------------------------------------------------------------------
// MLP head: fc1 (128->64, relu) + 5 x fc (64->64, relu). Single block.
// ---------------------------------------------------------------------------
__global__ void __launch_bounds__(512)
mlp_kernel(const float* __restrict__ fcW1, const float* __restrict__ fcb1,
           const float* __restrict__ fcW,  const float* __restrict__ fcb,
           int tower)
{
    __shared__ float ha[G_GRAPHS * OUT_DIM];
    __shared__ float hb[G_GRAPHS * OUT_DIM];
    int t = threadIdx.x;

    for (int idx = t; idx < G_GRAPHS * OUT_DIM; idx += 512) {
        int g = idx >> 6, o = idx & 63;
        float ic = g_cnt[g];
        ic = 1.0f / fmaxf(ic, 1.0f);
        float s = fcb1[o];
        #pragma unroll 4
        for (int k = 0; k < HID; ++k)
            s += g_pooled[g * HID + k] * ic * fcW1[k * OUT_DIM + o];
        ha[idx] = fmaxf(s, 0.0f);
    }
    __syncthreads();

    float* srcb = ha;
    float* dstb = hb;
    for (int L = 0; L < 5; ++L) {
        const float* Wp = fcW + L * OUT_DIM * OUT_DIM;
        const float* bp = fcb + L * OUT_DIM;
        for (int idx = t; idx < G_GRAPHS * OUT_DIM; idx += 512) {
            int g = idx >> 6, o = idx & 63;
            float s = bp[o];
            #pragma unroll 8
            for (int k = 0; k < OUT_DIM; ++k)
                s += srcb[g * OUT_DIM + k] * Wp[k * OUT_DIM + o];
            dstb[idx] = fmaxf(s, 0.0f);
        }
        __syncthreads();
        float* tmp = srcb; srcb = dstb; dstb = tmp;
    }

    for (int idx = t; idx < G_GRAPHS * OUT_DIM; idx += 512)
        g_h[tower][idx] = srcb[idx];
}

__global__ void final_kernel(float* __restrict__ out) {
    int g = threadIdx.x;
    if (g < G_GRAPHS) {
        float s = 0.0f;
        #pragma unroll 8
        for (int k = 0; k < OUT_DIM; ++k) {
            float d = g_h[0][g * OUT_DIM + k] - g_h[1][g * OUT_DIM + k];
            s += d * d;
        }
        out[g] = sqrtf(s);
    }
}

// ---------------------------------------------------------------------------
// Host launcher
// ---------------------------------------------------------------------------
extern "C" void kernel_launch(void* const* d_in, const int* in_sizes, int n_in,
                              void* d_out, int out_size)
{
    const float* x1  = (const float*)d_in[0];
    const int*   ei1 = (const int*)  d_in[1];
    const float* ea1 = (const float*)d_in[2];
    const int*   bt1 = (const int*)  d_in[3];
    const float* x2  = (const float*)d_in[4];
    const int*   ei2 = (const int*)  d_in[5];
    const float* ea2 = (const float*)d_in[6];
    const int*   bt2 = (const int*)  d_in[7];
    const float* convW = (const float*)d_in[8];
    const float* convB = (const float*)d_in[9];
    const float* fcW1  = (const float*)d_in[10];
    const float* fcb1  = (const float*)d_in[11];
    const float* fcW   = (const float*)d_in[12];
    const float* fcb   = (const float*)d_in[13];

    const bool ACTS[6] = { true, true, false, true, true, true };

    cudaFuncSetAttribute(gemm_kernel,
                         cudaFuncAttributeMaxDynamicSharedMemorySize,
                         GEMM_SMEM_BYTES);

    const int NB256_N = (N_NODES + 255) / 256;
    const int NB256_E = (N_EDGES + 255) / 256;
    const int GEMM_BLOCKS = (N_NODES + 127) / 128;
    const int AGG_BLOCKS  = (N_NODES * 16 + 255) / 256;
    const int POOL_BLOCKS = (N_NODES + POOL_CHUNK - 1) / POOL_CHUNK;

    for (int tower = 0; tower < 2; ++tower) {
        const float* x  = tower ? x2  : x1;
        const int*   ei = tower ? ei2 : ei1;
        const float* ea = tower ? ea2 : ea1;
        const int*   bt = tower ? bt2 : bt1;

        // Build dst-sorted CSR + norms (once per tower)
        zero_deg_kernel<<<NB256_N, 256>>>();
        deg_count_kernel<<<NB256_E, 256>>>(ei, ea);
        dinv_kernel<<<NB256_N, 256>>>();
        scan_block_kernel<<<N_SCAN_BLOCKS, SCAN_BLK>>>();
        scan_top_kernel<<<1, 32>>>();
        scan_add_kernel<<<NB256_N, 256>>>();
        scatter_kernel<<<NB256_E, 256>>>(ei, ea);

        // x -> fp16
        conv_x_kernel<<<(N_NODES * 32 + 255) / 256, 256>>>(x);

        for (int L = 0; L < 6; ++L) {
            gemm_kernel<<<GEMM_BLOCKS, 256, GEMM_SMEM_BYTES>>>(
                convW + (size_t)L * HID * HID);
            agg_kernel<<<AGG_BLOCKS, 256>>>(convB + L * HID, ACTS[L] ? 1 : 0);
        }

        pool_zero_kernel<<<(G_GRAPHS * HID + 255) / 256, 256>>>();
        pool_kernel<<<POOL_BLOCKS, 128>>>(bt);
        mlp_kernel<<<1, 512>>>(fcW1, fcb1, fcW, fcb, tower);
    }

    final_kernel<<<1, 64>>>((float*)d_out);
}

// round 9
// speedup vs baseline: 4.1994x; 1.1500x over previous
#include <cuda_runtime.h>
#include <cuda_fp16.h>
#include <math.h>

// Problem constants (fixed by the dataset)
#define N_NODES 100000
#define N_TOT   200000            // both towers fused
#define N_EDGES 1600000
#define E_TOT   3200000
#define G_GRAPHS 64
#define HID 128
#define OUT_DIM 64

#define SCAN_BLK 1024
#define N_SCAN_BLOCKS ((N_TOT + SCAN_BLK - 1) / SCAN_BLK)

// ---------------------------------------------------------------------------
// Scratch (device globals; allocation-free per harness rules)
// ---------------------------------------------------------------------------
__device__ __half g_bufAh[N_TOT * HID];     // node features (fp16), both towers
__device__ __half g_bufBh[N_TOT * HID];     // xw = x @ W (fp16)
__device__ float g_deg[N_TOT];
__device__ float g_dinv[N_TOT];
__device__ int   g_count[N_TOT];            // counts, then cursor
__device__ int   g_off[N_TOT + 1];          // CSR offsets (by global dst)
__device__ int   g_blocksum[N_SCAN_BLOCKS];
__device__ int   g_srcs[E_TOT];             // global src per sorted edge
__device__ float g_nrm[E_TOT];              // norm per sorted edge
__device__ float g_pooled[2 * G_GRAPHS * HID];
__device__ float g_cnt[2 * G_GRAPHS];
__device__ float g_h[2][G_GRAPHS * OUT_DIM];

// ---------------------------------------------------------------------------
// fp32 -> fp16 conversion of input features (both towers)
// ---------------------------------------------------------------------------
__global__ void conv_x_kernel(const float* __restrict__ x1,
                              const float* __restrict__ x2) {
    int i = blockIdx.x * blockDim.x + threadIdx.x;   // per 4 elements
    if (i < N_TOT * 32) {
        const float* x = (i < N_NODES * 32) ? x1 : x2;
        int li = (i < N_NODES * 32) ? i : (i - N_NODES * 32);
        float4 v = ((const float4*)x)[li];
        uint2 o;
        *(__half2*)&o.x = __floats2half2_rn(v.x, v.y);
        *(__half2*)&o.y = __floats2half2_rn(v.z, v.w);
        ((uint2*)g_bufAh)[i] = o;
    }
}

// ---------------------------------------------------------------------------
// Degree + counts (both edge lists, global node ids)
// ---------------------------------------------------------------------------
__global__ void zero_deg_kernel() {
    int i = blockIdx.x * blockDim.x + threadIdx.x;
    if (i < N_TOT) { g_deg[i] = 0.0f; g_count[i] = 0; }
}

__global__ void deg_count_kernel(const int* __restrict__ ei1,
                                 const float* __restrict__ ea1,
                                 const int* __restrict__ ei2,
                                 const float* __restrict__ ea2) {
    int e = blockIdx.x * blockDim.x + threadIdx.x;
    if (e < E_TOT) {
        int tower = (e >= N_EDGES) ? 1 : 0;
        int le = e - tower * N_EDGES;
        const int* ei = tower ? ei2 : ei1;
        const float* ea = tower ? ea2 : ea1;
        int di = ei[N_EDGES + le] + tower * N_NODES;
        atomicAdd(&g_deg[di], ea[le]);
        atomicAdd(&g_count[di], 1);
    }
}

__global__ void dinv_kernel() {
    int i = blockIdx.x * blockDim.x + threadIdx.x;
    if (i < N_TOT) g_dinv[i] = rsqrtf(g_deg[i] + 1.0f);
}

// ---------------------------------------------------------------------------
// Exclusive scan of g_count -> g_off
// ---------------------------------------------------------------------------
__global__ void __launch_bounds__(SCAN_BLK)
scan_block_kernel() {
    __shared__ int s[SCAN_BLK];
    int i = blockIdx.x * SCAN_BLK + threadIdx.x;
    int v = (i < N_TOT) ? g_count[i] : 0;
    s[threadIdx.x] = v;
    __syncthreads();
    #pragma unroll
    for (int d = 1; d < SCAN_BLK; d <<= 1) {
        int t = (threadIdx.x >= d) ? s[threadIdx.x - d] : 0;
        __syncthreads();
        s[threadIdx.x] += t;
        __syncthreads();
    }
    if (i < N_TOT) g_off[i] = s[threadIdx.x] - v;
    if (threadIdx.x == SCAN_BLK - 1) g_blocksum[blockIdx.x] = s[threadIdx.x];
}

__global__ void scan_top_kernel() {
    if (threadIdx.x == 0) {
        int run = 0;
        for (int b = 0; b < N_SCAN_BLOCKS; ++b) {
            int t = g_blocksum[b];
            g_blocksum[b] = run;
            run += t;
        }
        g_off[N_TOT] = run;
    }
}

__global__ void scan_add_kernel() {
    int i = blockIdx.x * blockDim.x + threadIdx.x;
    if (i < N_TOT) {
        int o = g_off[i] + g_blocksum[i >> 10];
        g_off[i] = o;
        g_count[i] = o;
    }
}

__global__ void scatter_kernel(const int* __restrict__ ei1,
                               const float* __restrict__ ea1,
                               const int* __restrict__ ei2,
                               const float* __restrict__ ea2) {
    int e = blockIdx.x * blockDim.x + threadIdx.x;
    if (e < E_TOT) {
        int tower = (e >= N_EDGES) ? 1 : 0;
        int le = e - tower * N_EDGES;
        const int* ei = tower ? ei2 : ei1;
        const float* ea = tower ? ea2 : ea1;
        int si = ei[le] + tower * N_NODES;
        int di = ei[N_EDGES + le] + tower * N_NODES;
        int pos = atomicAdd(&g_count[di], 1);
        g_srcs[pos] = si;
        g_nrm[pos]  = g_dinv[si] * ea[le] * g_dinv[di];
    }
}

// ---------------------------------------------------------------------------
// GEMM v4 (HFMA2, reduced registers): bufB[n,c] = sum_k bufA[n,k] * W[k,c]
// Block tile 128(M) x 64(N); grid = (row blocks, 2 col halves).
// 256 threads, 8 rows x 4 cols per thread.
// X in smem as half2 row-pairs [k][rp] (32KB); W slice as half2 [k][cp] (16KB).
// fp16 accumulate over chunks of 8 k, promoted to fp32.
// ---------------------------------------------------------------------------
#define XSTR2 64
#define WSTR2 32
#define GEMM_SMEM_BYTES (HID * XSTR2 * 4 + HID * WSTR2 * 4)   // 32KB + 16KB

__global__ void __launch_bounds__(256)
gemm_kernel(const float* __restrict__ W)
{
    extern __shared__ __half2 smem2[];
    __half2* sX2 = smem2;               // [k*XSTR2 + rp]
    __half2* sW2 = smem2 + HID * XSTR2; // [k*WSTR2 + cp]

    const int tid  = threadIdx.x;
    const int row0 = blockIdx.x * 128;
    const int gy   = blockIdx.y;        // column half: cols gy*64 .. gy*64+63

    // Load W slice (128 k x 64 cols), convert fp32 -> half2 col-pairs
    {
        const float4* W4 = (const float4*)W;
        #pragma unroll
        for (int i = 0; i < 8; ++i) {
            int idx = tid + i * 256;     // 0..2047
            int k  = idx >> 4;           // 16 float4 per k-row slice
            int c4 = idx & 15;
            float4 v = W4[k * 32 + gy * 16 + c4];
            uint2 o;
            *(__half2*)&o.x = __floats2half2_rn(v.x, v.y);
            *(__half2*)&o.y = __floats2half2_rn(v.z, v.w);
            *(uint2*)&sW2[k * WSTR2 + c4 * 2] = o;
        }
    }

    // Load X tile: 128 rows x 128 k (fp16), pack into [k][rowpair] half2.
    {
        const uint4* Xg = (const uint4*)g_bufAh;   // 8 halfs per uint4
        #pragma unroll
        for (int i = 0; i < 4; ++i) {
            int idx = tid + i * 256;      // 0..1023
            int rp  = idx & 63;
            int k8  = idx >> 6;
            int r0  = row0 + rp * 2;
            uint4 ua = make_uint4(0u, 0u, 0u, 0u);
            uint4 ub = make_uint4(0u, 0u, 0u, 0u);
            if (r0 < N_TOT)     ua = Xg[(size_t)r0 * 16 + k8];
            if (r0 + 1 < N_TOT) ub = Xg[(size_t)(r0 + 1) * 16 + k8];
            const __half2* pa = (const __half2*)&ua;
            const __half2* pb = (const __half2*)&ub;
            #pragma unroll
            for (int t2 = 0; t2 < 4; ++t2) {
                __half2 lo = __lows2half2(pa[t2], pb[t2]);
                __half2 hi = __highs2half2(pa[t2], pb[t2]);
                sX2[(k8 * 8 + t2 * 2 + 0) * XSTR2 + rp] = lo;
                sX2[(k8 * 8 + t2 * 2 + 1) * XSTR2 + rp] = hi;
            }
        }
    }
    __syncthreads();

    const int tx = tid & 15;   // cols tx*4 .. tx*4+3 within the 64-col slice
    const int ty = tid >> 4;   // rows ty*4 and 64+ty*4

    float accf[8][4];
    #pragma unroll
    for (int i = 0; i < 8; ++i)
        #pragma unroll
        for (int j = 0; j < 4; ++j) accf[i][j] = 0.0f;

    #pragma unroll
    for (int kc = 0; kc < 16; ++kc) {        // 16 chunks of 8 k
        __half2 acc2[8][2];
        #pragma unroll
        for (int i = 0; i < 8; ++i) {
            acc2[i][0] = __floats2half2_rn(0.0f, 0.0f);
            acc2[i][1] = __floats2half2_rn(0.0f, 0.0f);
        }

        #pragma unroll
        for (int kk = 0; kk < 8; ++kk) {
            int k = kc * 8 + kk;
            __half2 xa = sX2[k * XSTR2 + ty * 2];
            __half2 xb = sX2[k * XSTR2 + ty * 2 + 1];
            __half2 xc = sX2[k * XSTR2 + 32 + ty * 2];
            __half2 xd = sX2[k * XSTR2 + 32 + ty * 2 + 1];
            __half2 xr[8];
            xr[0] = __half2half2(__low2half(xa));
            xr[1] = __half2half2(__high2half(xa));
            xr[2] = __half2half2(__low2half(xb));
            xr[3] = __half2half2(__high2half(xb));
            xr[4] = __half2half2(__low2half(xc));
            xr[5] = __half2half2(__high2half(xc));
            xr[6] = __half2half2(__low2half(xd));
            xr[7] = __half2half2(__high2half(xd));

            __half2 wr0 = sW2[k * WSTR2 + tx * 2];
            __half2 wr1 = sW2[k * WSTR2 + tx * 2 + 1];

            #pragma unroll
            for (int i = 0; i < 8; ++i) {
                acc2[i][0] = __hfma2(xr[i], wr0, acc2[i][0]);
                acc2[i][1] = __hfma2(xr[i], wr1, acc2[i][1]);
            }
        }

        #pragma unroll
        for (int i = 0; i < 8; ++i) {
            float2 f0 = __half22float2(acc2[i][0]);
            float2 f1 = __half22float2(acc2[i][1]);
            accf[i][0] += f0.x; accf[i][1] += f0.y;
            accf[i][2] += f1.x; accf[i][3] += f1.y;
        }
    }

    // Epilogue: fp32 acc -> fp16 global
    const int col0 = gy * 64 + tx * 4;
    #pragma unroll
    for (int i = 0; i < 8; ++i) {
        int r = (i < 4) ? (ty * 4 + i) : (64 + ty * 4 + i - 4);
        int grow = row0 + r;
        if (grow < N_TOT) {
            uint2 o;
            *(__half2*)&o.x = __floats2half2_rn(accf[i][0], accf[i][1]);
            *(__half2*)&o.y = __floats2half2_rn(accf[i][2], accf[i][3]);
            *(uint2*)&g_bufBh[(size_t)grow * HID + col0] = o;
        }
    }
}

// ---------------------------------------------------------------------------
// Aggregation: HALF-WARP per destination node (16 lanes x 8 channels).
// out = act( bias + dinv*dinv * xw[self] + sum_j nrm[j] * xw[src[j]] )
// ---------------------------------------------------------------------------
__device__ __forceinline__ void fma8(float* a, const uint4& v, float n) {
    const __half2* p = (const __half2*)&v;
    float2 q0 = __half22float2(p[0]);
    float2 q1 = __half22float2(p[1]);
    float2 q2 = __half22float2(p[2]);
    float2 q3 = __half22float2(p[3]);
    a[0] += n * q0.x; a[1] += n * q0.y;
    a[2] += n * q1.x; a[3] += n * q1.y;
    a[4] += n * q2.x; a[5] += n * q2.y;
    a[6] += n * q3.x; a[7] += n * q3.y;
}

__global__ void __launch_bounds__(256)
agg_kernel(const float* __restrict__ bias, int act)
{
    int node = (blockIdx.x * blockDim.x + threadIdx.x) >> 4;  // half-warp id
    int ln   = threadIdx.x & 15;
    if (node >= N_TOT) return;

    const uint4* xw = (const uint4*)g_bufBh;

    int beg = g_off[node];
    int end = g_off[node + 1];

    float s = g_dinv[node];
    s = s * s;
    float4 b0 = ((const float4*)bias)[ln * 2];
    float4 b1 = ((const float4*)bias)[ln * 2 + 1];
    float a[8] = { b0.x, b0.y, b0.z, b0.w, b1.x, b1.y, b1.z, b1.w };

    uint4 self = xw[(size_t)node * 16 + ln];
    fma8(a, self, s);

    int j = beg;
    for (; j + 1 < end; j += 2) {
        int   s0 = g_srcs[j];
        int   s1 = g_srcs[j + 1];
        float n0 = g_nrm[j];
        float n1 = g_nrm[j + 1];
        uint4 v0 = xw[(size_t)s0 * 16 + ln];
        uint4 v1 = xw[(size_t)s1 * 16 + ln];
        fma8(a, v0, n0);
        fma8(a, v1, n1);
    }
    if (j < end) {
        int   s0 = g_srcs[j];
        float n0 = g_nrm[j];
        uint4 v0 = xw[(size_t)s0 * 16 + ln];
        fma8(a, v0, n0);
    }

    if (act) {
        #pragma unroll
        for (int i = 0; i < 8; ++i) a[i] = tanhf(a[i]);
    }
    uint4 o;
    *(__half2*)&o.x = __floats2half2_rn(a[0], a[1]);
    *(__half2*)&o.y = __floats2half2_rn(a[2], a[3]);
    *(__half2*)&o.z = __floats2half2_rn(a[4], a[5]);
    *(__half2*)&o.w = __floats2half2_rn(a[6], a[7]);
    ((uint4*)g_bufAh)[(size_t)node * 16 + ln] = o;
}

// ---------------------------------------------------------------------------
// Global mean pool (batch sorted per tower). grid = 2 * POOL_BLOCKS_T.
// ---------------------------------------------------------------------------
#define POOL_CHUNK 256
#define POOL_BLOCKS_T ((N_NODES + POOL_CHUNK - 1) / POOL_CHUNK)

__global__ void pool_zero_kernel() {
    int i = blockIdx.x * blockDim.x + threadIdx.x;
    if (i < 2 * G_GRAPHS * HID) g_pooled[i] = 0.0f;
    if (i < 2 * G_GRAPHS) g_cnt[i] = 0.0f;
}

__global__ void pool_kernel(const int* __restrict__ batch1,
                            const int* __restrict__ batch2) {
    int tower = (blockIdx.x >= POOL_BLOCKS_T) ? 1 : 0;
    const int* batch = tower ? batch2 : batch1;
    int blk = blockIdx.x - tower * POOL_BLOCKS_T;
    int c  = threadIdx.x;
    int n0 = blk * POOL_CHUNK;
    int n1 = n0 + POOL_CHUNK;
    if (n1 > N_NODES) n1 = N_NODES;
    if (n0 >= N_NODES) return;

    int gbase = tower * G_GRAPHS;
    size_t nodeoff = (size_t)tower * N_NODES;

    float acc = 0.0f;
    int cur = batch[n0];
    int run = 0;
    for (int n = n0; n < n1; ++n) {
        int g = batch[n];
        if (g != cur) {
            atomicAdd(&g_pooled[(gbase + cur) * HID + c], acc);
            if (c == 0) atomicAdd(&g_cnt[gbase + cur], (float)run);
            acc = 0.0f; run = 0; cur = g;
        }
        acc += __half2float(g_bufAh[(nodeoff + n) * HID + c]);
        run++;
    }
    atomicAdd(&g_pooled[(gbase + cur) * HID + c], acc);
    if (c == 0) atomicAdd(&g_cnt[gbase + cur], (float)run);
}

// ---------------------------------------------------------------------------
// MLP head: fc1 (128->64, relu) + 5 x fc (64->64, relu). grid = 2 (towers).
// ---------------------------------------------------------------------------
__global__ void __launch_bounds__(512)
mlp_kernel(const float* __restrict__ fcW1, const float* __restrict__ fcb1,
           const float* __restrict__ fcW,  const float* __restrict__ fcb)
{
    __shared__ float ha[G_GRAPHS * OUT_DIM];
    __shared__ float hb[G_GRAPHS * OUT_DIM];
    int t = threadIdx.x;
    int tower = blockIdx.x;
    int gbase = tower * G_GRAPHS;

    for (int idx = t; idx < G_GRAPHS * OUT_DIM; idx += 512) {
        int g = idx >> 6, o = idx & 63;
        float ic = g_cnt[gbase + g];
        ic = 1.0f / fmaxf(ic, 1.0f);
        float s = fcb1[o];
        #pragma unroll 4
        for (int k = 0; k < HID; ++k)
            s += g_pooled[(gbase + g) * HID + k] * ic * fcW1[k * OUT_DIM + o];
        ha[idx] = fmaxf(s, 0.0f);
    }
    __syncthreads();

    float* srcb = ha;
    float* dstb = hb;
    for (int L = 0; L < 5; ++L) {
        const float* Wp = fcW + L * OUT_DIM * OUT_DIM;
        const float* bp = fcb + L * OUT_DIM;
        for (int idx = t; idx < G_GRAPHS * OUT_DIM; idx += 512) {
            int g = idx >> 6, o = idx & 63;
            float s = bp[o];
            #pragma unroll 8
            for (int k = 0; k < OUT_DIM; ++k)
                s += srcb[g * OUT_DIM + k] * Wp[k * OUT_DIM + o];
            dstb[idx] = fmaxf(s, 0.0f);
        }
        __syncthreads();
        float* tmp = srcb; srcb = dstb; dstb = tmp;
    }

    for (int idx = t; idx < G_GRAPHS * OUT_DIM; idx += 512)
        g_h[tower][idx] = srcb[idx];
}

__global__ void final_kernel(float* __restrict__ out) {
    int g = threadIdx.x;
    if (g < G_GRAPHS) {
        float s = 0.0f;
        #pragma unroll 8
        for (int k = 0; k < OUT_DIM; ++k) {
            float d = g_h[0][g * OUT_DIM + k] - g_h[1][g * OUT_DIM + k];
            s += d * d;
        }
        out[g] = sqrtf(s);
    }
}

// ---------------------------------------------------------------------------
// Host launcher
// ---------------------------------------------------------------------------
extern "C" void kernel_launch(void* const* d_in, const int* in_sizes, int n_in,
                              void* d_out, int out_size)
{
    const float* x1  = (const float*)d_in[0];
    const int*   ei1 = (const int*)  d_in[1];
    const float* ea1 = (const float*)d_in[2];
    const int*   bt1 = (const int*)  d_in[3];
    const float* x2  = (const float*)d_in[4];
    const int*   ei2 = (const int*)  d_in[5];
    const float* ea2 = (const float*)d_in[6];
    const int*   bt2 = (const int*)  d_in[7];
    const float* convW = (const float*)d_in[8];
    const float* convB = (const float*)d_in[9];
    const float* fcW1  = (const float*)d_in[10];
    const float* fcb1  = (const float*)d_in[11];
    const float* fcW   = (const float*)d_in[12];
    const float* fcb   = (const float*)d_in[13];

    const bool ACTS[6] = { true, true, false, true, true, true };

    cudaFuncSetAttribute(gemm_kernel,
                         cudaFuncAttributeMaxDynamicSharedMemorySize,
                         GEMM_SMEM_BYTES);

    const int NBN = (N_TOT + 255) / 256;
    const int NBE = (E_TOT + 255) / 256;
    const dim3 GEMM_GRID((N_TOT + 127) / 128, 2);
    const int AGG_BLOCKS = (N_TOT * 16) / 256;

    // Build unified dst-sorted CSR + norms (once; reused for 6 layers)
    zero_deg_kernel<<<NBN, 256>>>();
    deg_count_kernel<<<NBE, 256>>>(ei1, ea1, ei2, ea2);
    dinv_kernel<<<NBN, 256>>>();
    scan_block_kernel<<<N_SCAN_BLOCKS, SCAN_BLK>>>();
    scan_top_kernel<<<1, 32>>>();
    scan_add_kernel<<<NBN, 256>>>();
    scatter_kernel<<<NBE, 256>>>(ei1, ea1, ei2, ea2);

    // x -> fp16 (both towers)
    conv_x_kernel<<<(N_TOT * 32 + 255) / 256, 256>>>(x1, x2);

    for (int L = 0; L < 6; ++L) {
        gemm_kernel<<<GEMM_GRID, 256, GEMM_SMEM_BYTES>>>(
            convW + (size_t)L * HID * HID);
        agg_kernel<<<AGG_BLOCKS, 256>>>(convB + L * HID, ACTS[L] ? 1 : 0);
    }

    pool_zero_kernel<<<(2 * G_GRAPHS * HID + 255) / 256, 256>>>();
    pool_kernel<<<2 * POOL_BLOCKS_T, 128>>>(bt1, bt2);
    mlp_kernel<<<2, 512>>>(fcW1, fcb1, fcW, fcb);

    final_kernel<<<1, 64>>>((float*)d_out);
}

// round 10
// speedup vs baseline: 4.3240x; 1.0297x over previous
#include <cuda_runtime.h>
#include <cuda_fp16.h>
#include <math.h>

// Problem constants (fixed by the dataset)
#define N_NODES 100000
#define N_TOT   200000            // both towers fused
#define N_EDGES 1600000
#define E_TOT   3200000
#define G_GRAPHS 64
#define HID 128
#define OUT_DIM 64

#define SCAN_BLK 1024
#define N_SCAN_BLOCKS ((N_TOT + SCAN_BLK - 1) / SCAN_BLK)

// ---------------------------------------------------------------------------
// Scratch (device globals; allocation-free per harness rules)
// ---------------------------------------------------------------------------
__device__ __half g_bufAh[N_TOT * HID];     // node features (fp16), both towers
__device__ __half g_bufBh[N_TOT * HID];     // xw = x @ W (fp16)
__device__ float g_deg[N_TOT];
__device__ float g_dinv[N_TOT];
__device__ int   g_count[N_TOT];            // counts, then cursor
__device__ int   g_off[N_TOT + 1];          // CSR offsets (by global dst)
__device__ int   g_blocksum[N_SCAN_BLOCKS];
__device__ int   g_srcs[E_TOT];             // global src per sorted edge
__device__ float g_nrm[E_TOT];              // norm per sorted edge
__device__ float g_pooled[2 * G_GRAPHS * HID];
__device__ float g_cnt[2 * G_GRAPHS];
__device__ float g_h[2][G_GRAPHS * OUT_DIM];

// ---------------------------------------------------------------------------
// fp32 -> fp16 conversion of input features (both towers)
// ---------------------------------------------------------------------------
__global__ void conv_x_kernel(const float* __restrict__ x1,
                              const float* __restrict__ x2) {
    int i = blockIdx.x * blockDim.x + threadIdx.x;   // per 4 elements
    if (i < N_TOT * 32) {
        const float* x = (i < N_NODES * 32) ? x1 : x2;
        int li = (i < N_NODES * 32) ? i : (i - N_NODES * 32);
        float4 v = ((const float4*)x)[li];
        uint2 o;
        *(__half2*)&o.x = __floats2half2_rn(v.x, v.y);
        *(__half2*)&o.y = __floats2half2_rn(v.z, v.w);
        ((uint2*)g_bufAh)[i] = o;
    }
}

// ---------------------------------------------------------------------------
// Degree + counts (both edge lists, global node ids)
// ---------------------------------------------------------------------------
__global__ void zero_deg_kernel() {
    int i = blockIdx.x * blockDim.x + threadIdx.x;
    if (i < N_TOT) { g_deg[i] = 0.0f; g_count[i] = 0; }
}

__global__ void deg_count_kernel(const int* __restrict__ ei1,
                                 const float* __restrict__ ea1,
                                 const int* __restrict__ ei2,
                                 const float* __restrict__ ea2) {
    int e = blockIdx.x * blockDim.x + threadIdx.x;
    if (e < E_TOT) {
        int tower = (e >= N_EDGES) ? 1 : 0;
        int le = e - tower * N_EDGES;
        const int* ei = tower ? ei2 : ei1;
        const float* ea = tower ? ea2 : ea1;
        int di = ei[N_EDGES + le] + tower * N_NODES;
        atomicAdd(&g_deg[di], ea[le]);
        atomicAdd(&g_count[di], 1);
    }
}

// ---------------------------------------------------------------------------
// Exclusive scan of g_count -> g_off
// ---------------------------------------------------------------------------
__global__ void __launch_bounds__(SCAN_BLK)
scan_block_kernel() {
    __shared__ int s[SCAN_BLK];
    int i = blockIdx.x * SCAN_BLK + threadIdx.x;
    int v = (i < N_TOT) ? g_count[i] : 0;
    s[threadIdx.x] = v;
    __syncthreads();
    #pragma unroll
    for (int d = 1; d < SCAN_BLK; d <<= 1) {
        int t = (threadIdx.x >= d) ? s[threadIdx.x - d] : 0;
        __syncthreads();
        s[threadIdx.x] += t;
        __syncthreads();
    }
    if (i < N_TOT) g_off[i] = s[threadIdx.x] - v;
    if (threadIdx.x == SCAN_BLK - 1) g_blocksum[blockIdx.x] = s[threadIdx.x];
}

__global__ void scan_top_kernel() {
    if (threadIdx.x == 0) {
        int run = 0;
        for (int b = 0; b < N_SCAN_BLOCKS; ++b) {
            int t = g_blocksum[b];
            g_blocksum[b] = run;
            run += t;
        }
        g_off[N_TOT] = run;
    }
}

// also computes dinv (deg is final by now)
__global__ void scan_add_kernel() {
    int i = blockIdx.x * blockDim.x + threadIdx.x;
    if (i < N_TOT) {
        int o = g_off[i] + g_blocksum[i >> 10];
        g_off[i] = o;
        g_count[i] = o;
        g_dinv[i] = rsqrtf(g_deg[i] + 1.0f);
    }
}

__global__ void scatter_kernel(const int* __restrict__ ei1,
                               const float* __restrict__ ea1,
                               const int* __restrict__ ei2,
                               const float* __restrict__ ea2) {
    int e = blockIdx.x * blockDim.x + threadIdx.x;
    if (e < E_TOT) {
        int tower = (e >= N_EDGES) ? 1 : 0;
        int le = e - tower * N_EDGES;
        const int* ei = tower ? ei2 : ei1;
        const float* ea = tower ? ea2 : ea1;
        int si = ei[le] + tower * N_NODES;
        int di = ei[N_EDGES + le] + tower * N_NODES;
        int pos = atomicAdd(&g_count[di], 1);
        g_srcs[pos] = si;
        g_nrm[pos]  = g_dinv[si] * ea[le] * g_dinv[di];
    }
}

// ---------------------------------------------------------------------------
// GEMM v5 (HFMA2, pre-splatted X): bufB[n,c] = sum_k bufA[n,k] * W[k,c]
// Block tile 128(M) x 64(N); grid = (row blocks, 2 col halves).
// 256 threads, 8 rows x 4 cols per thread.
// X in smem as SPLATTED half2 (x,x): sXd[k*128 + r]  (64KB)
// W slice as half2 col-pairs:        sW2[k*32 + cp]  (16KB)
// Inner loop per k: 2 LDS.128 + 1 LDS.64 + 16 HFMA2, no extraction ops.
// fp16 accumulate over chunks of 8 k, promoted to fp32.
// ---------------------------------------------------------------------------
#define WSTR2 32
#define GEMM_SMEM_BYTES (HID * 128 * 4 + HID * WSTR2 * 4)   // 64KB + 16KB

__global__ void __launch_bounds__(256, 2)
gemm_kernel(const float* __restrict__ W)
{
    extern __shared__ __half2 smem2[];
    __half2* sXd = smem2;               // [k*128 + r], splatted
    __half2* sW2 = smem2 + HID * 128;   // [k*WSTR2 + cp]

    const int tid  = threadIdx.x;
    const int row0 = blockIdx.x * 128;
    const int gy   = blockIdx.y;        // column half

    // Load W slice (128 k x 64 cols), fp32 -> half2 col-pairs
    {
        const float4* W4 = (const float4*)W;
        #pragma unroll
        for (int i = 0; i < 8; ++i) {
            int idx = tid + i * 256;     // 0..2047
            int k  = idx >> 4;
            int c4 = idx & 15;
            float4 v = W4[k * 32 + gy * 16 + c4];
            uint2 o;
            *(__half2*)&o.x = __floats2half2_rn(v.x, v.y);
            *(__half2*)&o.y = __floats2half2_rn(v.z, v.w);
            *(uint2*)&sW2[k * WSTR2 + c4 * 2] = o;
        }
    }

    // Load X tile (128 rows x 128 k fp16), splat each value into sXd[k][r]
    {
        const uint4* Xg = (const uint4*)g_bufAh;   // 8 halfs per uint4
        #pragma unroll
        for (int i = 0; i < 8; ++i) {
            int idx = tid + i * 256;      // 0..2047
            int r   = idx & 127;
            int k8  = idx >> 7;           // 0..15, chunk of 8 k
            int grow = row0 + r;
            uint4 u = make_uint4(0u, 0u, 0u, 0u);
            if (grow < N_TOT) u = Xg[(size_t)grow * 16 + k8];
            const __half* ph = (const __half*)&u;
            #pragma unroll
            for (int t = 0; t < 8; ++t)
                sXd[(k8 * 8 + t) * 128 + r] = __half2half2(ph[t]);
        }
    }
    __syncthreads();

    const int tx = tid & 15;   // cols tx*4 .. tx*4+3 within the 64-col slice
    const int ty = tid >> 4;   // rows ty*4 and 64+ty*4

    float accf[8][4];
    #pragma unroll
    for (int i = 0; i < 8; ++i)
        #pragma unroll
        for (int j = 0; j < 4; ++j) accf[i][j] = 0.0f;

    #pragma unroll
    for (int kc = 0; kc < 16; ++kc) {        // 16 chunks of 8 k
        __half2 acc2[8][2];
        #pragma unroll
        for (int i = 0; i < 8; ++i) {
            acc2[i][0] = __floats2half2_rn(0.0f, 0.0f);
            acc2[i][1] = __floats2half2_rn(0.0f, 0.0f);
        }

        #pragma unroll
        for (int kk = 0; kk < 8; ++kk) {
            int k = kc * 8 + kk;
            uint4 xva = *(const uint4*)&sXd[k * 128 + ty * 4];
            uint4 xvb = *(const uint4*)&sXd[k * 128 + 64 + ty * 4];
            const __half2* pa = (const __half2*)&xva;
            const __half2* pb = (const __half2*)&xvb;

            __half2 wr0 = sW2[k * WSTR2 + tx * 2];
            __half2 wr1 = sW2[k * WSTR2 + tx * 2 + 1];

            #pragma unroll
            for (int i = 0; i < 4; ++i) {
                acc2[i][0] = __hfma2(pa[i], wr0, acc2[i][0]);
                acc2[i][1] = __hfma2(pa[i], wr1, acc2[i][1]);
                acc2[i + 4][0] = __hfma2(pb[i], wr0, acc2[i + 4][0]);
                acc2[i + 4][1] = __hfma2(pb[i], wr1, acc2[i + 4][1]);
            }
        }

        #pragma unroll
        for (int i = 0; i < 8; ++i) {
            float2 f0 = __half22float2(acc2[i][0]);
            float2 f1 = __half22float2(acc2[i][1]);
            accf[i][0] += f0.x; accf[i][1] += f0.y;
            accf[i][2] += f1.x; accf[i][3] += f1.y;
        }
    }

    // Epilogue: fp32 acc -> fp16 global
    const int col0 = gy * 64 + tx * 4;
    #pragma unroll
    for (int i = 0; i < 8; ++i) {
        int r = (i < 4) ? (ty * 4 + i) : (64 + ty * 4 + i - 4);
        int grow = row0 + r;
        if (grow < N_TOT) {
            uint2 o;
            *(__half2*)&o.x = __floats2half2_rn(accf[i][0], accf[i][1]);
            *(__half2*)&o.y = __floats2half2_rn(accf[i][2], accf[i][3]);
            *(uint2*)&g_bufBh[(size_t)grow * HID + col0] = o;
        }
    }
}

// ---------------------------------------------------------------------------
// Aggregation: HALF-WARP per destination node (16 lanes x 8 channels).
// out = act( bias + dinv*dinv * xw[self] + sum_j nrm[j] * xw[src[j]] )
// ---------------------------------------------------------------------------
__device__ __forceinline__ void fma8(float* a, const uint4& v, float n) {
    const __half2* p = (const __half2*)&v;
    float2 q0 = __half22float2(p[0]);
    float2 q1 = __half22float2(p[1]);
    float2 q2 = __half22float2(p[2]);
    float2 q3 = __half22float2(p[3]);
    a[0] += n * q0.x; a[1] += n * q0.y;
    a[2] += n * q1.x; a[3] += n * q1.y;
    a[4] += n * q2.x; a[5] += n * q2.y;
    a[6] += n * q3.x; a[7] += n * q3.y;
}

__global__ void __launch_bounds__(256)
agg_kernel(const float* __restrict__ bias, int act)
{
    int node = (blockIdx.x * blockDim.x + threadIdx.x) >> 4;  // half-warp id
    int ln   = threadIdx.x & 15;
    if (node >= N_TOT) return;

    const uint4* xw = (const uint4*)g_bufBh;

    int beg = g_off[node];
    int end = g_off[node + 1];

    float s = g_dinv[node];
    s = s * s;
    float4 b0 = ((const float4*)bias)[ln * 2];
    float4 b1 = ((const float4*)bias)[ln * 2 + 1];
    float a[8] = { b0.x, b0.y, b0.z, b0.w, b1.x, b1.y, b1.z, b1.w };

    uint4 self = xw[(size_t)node * 16 + ln];
    fma8(a, self, s);

    int j = beg;
    for (; j + 1 < end; j += 2) {
        int   s0 = g_srcs[j];
        int   s1 = g_srcs[j + 1];
        float n0 = g_nrm[j];
        float n1 = g_nrm[j + 1];
        uint4 v0 = xw[(size_t)s0 * 16 + ln];
        uint4 v1 = xw[(size_t)s1 * 16 + ln];
        fma8(a, v0, n0);
        fma8(a, v1, n1);
    }
    if (j < end) {
        int   s0 = g_srcs[j];
        float n0 = g_nrm[j];
        uint4 v0 = xw[(size_t)s0 * 16 + ln];
        fma8(a, v0, n0);
    }

    if (act) {
        #pragma unroll
        for (int i = 0; i < 8; ++i) a[i] = tanhf(a[i]);
    }
    uint4 o;
    *(__half2*)&o.x = __floats2half2_rn(a[0], a[1]);
    *(__half2*)&o.y = __floats2half2_rn(a[2], a[3]);
    *(__half2*)&o.z = __floats2half2_rn(a[4], a[5]);
    *(__half2*)&o.w = __floats2half2_rn(a[6], a[7]);
    ((uint4*)g_bufAh)[(size_t)node * 16 + ln] = o;
}

// ---------------------------------------------------------------------------
// Global mean pool (batch sorted per tower). grid = 2 * POOL_BLOCKS_T.
// ---------------------------------------------------------------------------
#define POOL_CHUNK 128
#define POOL_BLOCKS_T ((N_NODES + POOL_CHUNK - 1) / POOL_CHUNK)

__global__ void pool_zero_kernel() {
    int i = blockIdx.x * blockDim.x + threadIdx.x;
    if (i < 2 * G_GRAPHS * HID) g_pooled[i] = 0.0f;
    if (i < 2 * G_GRAPHS) g_cnt[i] = 0.0f;
}

__global__ void pool_kernel(const int* __restrict__ batch1,
                            const int* __restrict__ batch2) {
    int tower = (blockIdx.x >= POOL_BLOCKS_T) ? 1 : 0;
    const int* batch = tower ? batch2 : batch1;
    int blk = blockIdx.x - tower * POOL_BLOCKS_T;
    int c  = threadIdx.x;
    int n0 = blk * POOL_CHUNK;
    int n1 = n0 + POOL_CHUNK;
    if (n1 > N_NODES) n1 = N_NODES;
    if (n0 >= N_NODES) return;

    int gbase = tower * G_GRAPHS;
    size_t nodeoff = (size_t)tower * N_NODES;

    float acc = 0.0f;
    int cur = batch[n0];
    int run = 0;
    for (int n = n0; n < n1; ++n) {
        int g = batch[n];
        if (g != cur) {
            atomicAdd(&g_pooled[(gbase + cur) * HID + c], acc);
            if (c == 0) atomicAdd(&g_cnt[gbase + cur], (float)run);
            acc = 0.0f; run = 0; cur = g;
        }
        acc += __half2float(g_bufAh[(nodeoff + n) * HID + c]);
        run++;
    }
    atomicAdd(&g_pooled[(gbase + cur) * HID + c], acc);
    if (c == 0) atomicAdd(&g_cnt[gbase + cur], (float)run);
}

// ---------------------------------------------------------------------------
// MLP head: fc1 (128->64, relu) + 5 x fc (64->64, relu). grid = 2 (towers).
// ---------------------------------------------------------------------------
__global__ void __launch_bounds__(512)
mlp_kernel(const float* __restrict__ fcW1, const float* __restrict__ fcb1,
           const float* __restrict__ fcW,  const float* __restrict__ fcb)
{
    __shared__ float ha[G_GRAPHS * OUT_DIM];
    __shared__ float hb[G_GRAPHS * OUT_DIM];
    int t = threadIdx.x;
    int tower = blockIdx.x;
    int gbase = tower * G_GRAPHS;

    for (int idx = t; idx < G_GRAPHS * OUT_DIM; idx += 512) {
        int g = idx >> 6, o = idx & 63;
        float ic = g_cnt[gbase + g];
        ic = 1.0f / fmaxf(ic, 1.0f);
        float s = fcb1[o];
        #pragma unroll 4
        for (int k = 0; k < HID; ++k)
            s += g_pooled[(gbase + g) * HID + k] * ic * fcW1[k * OUT_DIM + o];
        ha[idx] = fmaxf(s, 0.0f);
    }
    __syncthreads();

    float* srcb = ha;
    float* dstb = hb;
    for (int L = 0; L < 5; ++L) {
        const float* Wp = fcW + L * OUT_DIM * OUT_DIM;
        const float* bp = fcb + L * OUT_DIM;
        for (int idx = t; idx < G_GRAPHS * OUT_DIM; idx += 512) {
            int g = idx >> 6, o = idx & 63;
            float s = bp[o];
            #pragma unroll 8
            for (int k = 0; k < OUT_DIM; ++k)
                s += srcb[g * OUT_DIM + k] * Wp[k * OUT_DIM + o];
            dstb[idx] = fmaxf(s, 0.0f);
        }
        __syncthreads();
        float* tmp = srcb; srcb = dstb; dstb = tmp;
    }

    for (int idx = t; idx < G_GRAPHS * OUT_DIM; idx += 512)
        g_h[tower][idx] = srcb[idx];
}

__global__ void final_kernel(float* __restrict__ out) {
    int g = threadIdx.x;
    if (g < G_GRAPHS) {
        float s = 0.0f;
        #pragma unroll 8
        for (int k = 0; k < OUT_DIM; ++k) {
            float d = g_h[0][g * OUT_DIM + k] - g_h[1][g * OUT_DIM + k];
            s += d * d;
        }
        out[g] = sqrtf(s);
    }
}

// ---------------------------------------------------------------------------
// Host launcher
// ---------------------------------------------------------------------------
extern "C" void kernel_launch(void* const* d_in, const int* in_sizes, int n_in,
                              void* d_out, int out_size)
{
    const float* x1  = (const float*)d_in[0];
    const int*   ei1 = (const int*)  d_in[1];
    const float* ea1 = (const float*)d_in[2];
    const int*   bt1 = (const int*)  d_in[3];
    const float* x2  = (const float*)d_in[4];
    const int*   ei2 = (const int*)  d_in[5];
    const float* ea2 = (const float*)d_in[6];
    const int*   bt2 = (const int*)  d_in[7];
    const float* convW = (const float*)d_in[8];
    const float* convB = (const float*)d_in[9];
    const float* fcW1  = (const float*)d_in[10];
    const float* fcb1  = (const float*)d_in[11];
    const float* fcW   = (const float*)d_in[12];
    const float* fcb   = (const float*)d_in[13];

    const bool ACTS[6] = { true, true, false, true, true, true };

    cudaFuncSetAttribute(gemm_kernel,
                         cudaFuncAttributeMaxDynamicSharedMemorySize,
                         GEMM_SMEM_BYTES);

    const int NBN = (N_TOT + 255) / 256;
    const int NBE = (E_TOT + 255) / 256;
    const dim3 GEMM_GRID((N_TOT + 127) / 128, 2);
    const int AGG_BLOCKS = (N_TOT * 16) / 256;

    // Build unified dst-sorted CSR + norms (once; reused for 6 layers)
    zero_deg_kernel<<<NBN, 256>>>();
    deg_count_kernel<<<NBE, 256>>>(ei1, ea1, ei2, ea2);
    scan_block_kernel<<<N_SCAN_BLOCKS, SCAN_BLK>>>();
    scan_top_kernel<<<1, 32>>>();
    scan_add_kernel<<<NBN, 256>>>();
    scatter_kernel<<<NBE, 256>>>(ei1, ea1, ei2, ea2);

    // x -> fp16 (both towers)
    conv_x_kernel<<<(N_TOT * 32 + 255) / 256, 256>>>(x1, x2);

    for (int L = 0; L < 6; ++L) {
        gemm_kernel<<<GEMM_GRID, 256, GEMM_SMEM_BYTES>>>(
            convW + (size_t)L * HID * HID);
        agg_kernel<<<AGG_BLOCKS, 256>>>(convB + L * HID, ACTS[L] ? 1 : 0);
    }

    pool_zero_kernel<<<(2 * G_GRAPHS * HID + 255) / 256, 256>>>();
    pool_kernel<<<2 * POOL_BLOCKS_T, 128>>>(bt1, bt2);
    mlp_kernel<<<2, 512>>>(fcW1, fcb1, fcW, fcb);

    final_kernel<<<1, 64>>>((float*)d_out);
}